// round 13
// baseline (speedup 1.0000x reference)
#include <cuda_runtime.h>
#include <cuda_bf16.h>
#include <math.h>
#include <stdint.h>

#define NN 50000
#define EE 800000
#define ET 850000      // EE + NN self loops
#define ELINK 1000000
#define PI_2 1.57079632679489662f

// ---------------- device scratch (allocation-free contract) ----------------
__device__ float g_bufA[(size_t)NN * 256];  // h (fp32 trunk)
__device__ float g_bufD[(size_t)NN * 256];  // y / h1 / scratch
__device__ float g_bufE[(size_t)NN * 256];  // h2
__device__ float g_hf[(size_t)NN * 32];

__device__ __nv_bfloat16 g_xcat16[(size_t)NN * 384];
__device__ __nv_bfloat16 g_bA16[(size_t)NN * 256];
__device__ __nv_bfloat16 g_bB16[(size_t)NN * 256];  // hl / pre1-temp
__device__ __nv_bfloat16 g_bC16[(size_t)NN * 256];  // hr
__device__ __nv_bfloat16 g_bD16[(size_t)NN * 256];  // h1
__device__ __nv_bfloat16 g_bE16[(size_t)NN * 256];  // h2

// bf16 weight arena. LIN region holds per-layer fused [K=256, 512] matrices
// (cols 0-255 = lin_l, cols 256-511 = lin_r).
#define W16_PRE1 0
#define W16_PRE2 98304
#define W16_LIN  163840
#define W16_D2   688128
#define W16_D3   950272
#define W16_POST1 1212416
#define W16_TOTAL 1277952
__device__ __nv_bfloat16 g_w16[W16_TOTAL];
__device__ float g_blin[4 * 512];   // fused lin bias per layer

__device__ int g_deg[NN];
__device__ int g_off[NN + 1];
__device__ int g_pos[NN];
__device__ int g_csr_src[ET];
__device__ int g_bsum[64];
__device__ float g_red[131072];

// ---------------- weight conversion fp32 -> bf16 (+ fused lin layout) -------
__global__ void k_wconv(const float* p1, const float* p2, const float* ll,
                        const float* lr, const float* d2, const float* d3,
                        const float* po1, const float* llb, const float* lrb) {
    int i = blockIdx.x * blockDim.x + threadIdx.x;
    if (i >= W16_TOTAL + 2048) return;
    if (i >= W16_TOTAL) {
        int j = i - W16_TOTAL;
        int layer = j >> 9, c = j & 511;
        g_blin[j] = (c < 256) ? llb[layer * 256 + c] : lrb[layer * 256 + (c - 256)];
        return;
    }
    float v;
    if (i < W16_PRE2) v = p1[i - W16_PRE1];
    else if (i < W16_LIN) v = p2[i - W16_PRE2];
    else if (i < W16_D2) {
        int l = i - W16_LIN;
        int layer = l >> 17;
        int lm = l & 131071;
        int k = lm >> 9;
        int c = lm & 511;
        const float* src = (c < 256) ? ll : lr;
        v = src[layer * 65536 + k * 256 + (c & 255)];
    }
    else if (i < W16_D3) v = d2[i - W16_D2];
    else if (i < W16_POST1) v = d3[i - W16_D3];
    else v = po1[i - W16_POST1];
    g_w16[i] = __float2bfloat16(v);
}

// ---------------- CSR build ----------------
__global__ void k_init_deg() {
    int i = blockIdx.x * blockDim.x + threadIdx.x;
    if (i < NN) g_deg[i] = 1;  // self loop
}

__global__ void k_count(const int* __restrict__ ei) {
    int e = blockIdx.x * blockDim.x + threadIdx.x;
    if (e < EE) atomicAdd(&g_deg[ei[EE + e]], 1);
}

__global__ void k_scan1() {
    int b = blockIdx.x, t = threadIdx.x;
    int i = b * 1024 + t;
    int d = (i < NN) ? g_deg[i] : 0;
    int lane = t & 31, wid = t >> 5;
    int v = d;
#pragma unroll
    for (int o = 1; o < 32; o <<= 1) {
        int u = __shfl_up_sync(0xffffffffu, v, o);
        if (lane >= o) v += u;
    }
    __shared__ int ws[32];
    if (lane == 31) ws[wid] = v;
    __syncthreads();
    if (wid == 0) {
        int w = ws[lane];
#pragma unroll
        for (int o = 1; o < 32; o <<= 1) {
            int u = __shfl_up_sync(0xffffffffu, w, o);
            if (lane >= o) w += u;
        }
        ws[lane] = w;
    }
    __syncthreads();
    int incl = v + (wid ? ws[wid - 1] : 0);
    if (i < NN) g_off[i] = incl - d;
    if (t == 1023) g_bsum[b] = incl;
}

__global__ void k_scan2(int nblk) {
    int run = 0;
    for (int i = 0; i < nblk; i++) {
        int d = g_bsum[i];
        g_bsum[i] = run;
        run += d;
    }
}

__global__ void k_scan3() {
    int b = blockIdx.x, t = threadIdx.x;
    int i = b * 1024 + t;
    if (i < NN) {
        int off = g_off[i] + g_bsum[b];
        g_off[i] = off;
        g_pos[i] = off;
    }
    if (i == 0) g_off[NN] = ET;
}

__global__ void k_fill(const int* __restrict__ ei) {
    int i = blockIdx.x * blockDim.x + threadIdx.x;
    if (i < EE) {
        int s = ei[i];
        int d = ei[EE + i];
        int p = atomicAdd(&g_pos[d], 1);
        g_csr_src[p] = s;
    } else if (i < ET) {
        int n = i - EE;
        int p = atomicAdd(&g_pos[n], 1);
        g_csr_src[p] = n;
    }
}

// ---------------- time embedding + concat (bf16 out) ----------------
__global__ void k_te(const float* __restrict__ x, const float* __restrict__ t,
                     const float* __restrict__ tw, const float* __restrict__ tb) {
    int n = blockIdx.x;
    int j = threadIdx.x;
    if (j < 128) {
        g_xcat16[(size_t)n * 384 + j] = __float2bfloat16(x[(size_t)n * 128 + j]);
    } else {
        int jj = j - 128;
        float a = t[n] * (1.0f / 1000.0f);
        float sa, ca;
        sincosf(a * PI_2, &sa, &ca);
        float v = sa * tw[jj] + ca * tw[256 + jj] + a * tw[512 + jj] + tb[jj];
        v = v / (1.0f + __expf(-v));  // swish
        g_xcat16[(size_t)n * 384 + j] = __float2bfloat16(v);
    }
}

// ---------------- bf16 tensor-core GEMM, 3-stage pipeline (round-8 proven) --
#define A_STRIDE_B 80    // bytes per A smem row (64B data + 16B pad)
#define B_STRIDE_B 272   // bytes per B smem row (256B data + 16B pad)
#define A_BYTES (128 * A_STRIDE_B)   // 10240
#define B_BYTES (32 * B_STRIDE_B)    // 8704
#define STAGE_BYTES (A_BYTES + B_BYTES)
#define GEMM_SMEM_BYTES (3 * STAGE_BYTES)  // 56832

__global__ void __launch_bounds__(256, 2)
k_gemm_bf16(const __nv_bfloat16* __restrict__ A, const __nv_bfloat16* __restrict__ B,
            const float* __restrict__ bias, float* __restrict__ Cf,
            __nv_bfloat16* __restrict__ Ch, __nv_bfloat16* __restrict__ Ch2,
            const float* __restrict__ addC, int M, int K, int ldb,
            int relu, int red) {
    extern __shared__ char sm[];
    char* aBuf[3] = {sm, sm + STAGE_BYTES, sm + 2 * STAGE_BYTES};
    char* bBuf[3] = {sm + A_BYTES, sm + STAGE_BYTES + A_BYTES,
                     sm + 2 * STAGE_BYTES + A_BYTES};

    int tid = threadIdx.x;
    int lane = tid & 31;
    int w = tid >> 5;
    int wm = (w >> 2) * 64;
    int wn = (w & 3) * 32;
    int g = lane >> 2;
    int cc = lane & 3;
    int row0 = blockIdx.x * 128;
    int col0 = blockIdx.y * 128;

    __nv_bfloat16* Cht = (Ch2 && col0 >= 256) ? Ch2 : Ch;
    int cOff = (Ch2 && col0 >= 256) ? 256 : 0;

    float acc[4][4][4];
#pragma unroll
    for (int mt = 0; mt < 4; mt++)
#pragma unroll
        for (int nt = 0; nt < 4; nt++)
#pragma unroll
            for (int i = 0; i < 4; i++) acc[mt][nt][i] = 0.f;

    int NC = K >> 5;

    int a_row0 = tid >> 2, a_cw = tid & 3;
    int b_kr0 = tid >> 4, b_cw = tid & 15;

    int lm15 = lane & 15;
    int lhi = (lane >> 4) << 4;
    unsigned int a_lm_off = (unsigned int)((wm + lm15) * A_STRIDE_B + lhi);
    unsigned int b_lm_off = (unsigned int)(lm15 * B_STRIDE_B + wn * 2 + lhi);

#define ISSUE_CHUNK16(buf, kb)                                                        \
    {                                                                                 \
        char* as_ = aBuf[buf];                                                        \
        char* bs_ = bBuf[buf];                                                        \
        _Pragma("unroll") for (int p = 0; p < 2; p++) {                               \
            int row = a_row0 + p * 64;                                                \
            const __nv_bfloat16* src = A + (size_t)(row0 + row) * K + (kb) + a_cw * 8;\
            unsigned int dst = (unsigned int)__cvta_generic_to_shared(                \
                as_ + row * A_STRIDE_B + a_cw * 16);                                  \
            int sz = (row0 + row < M) ? 16 : 0;                                       \
            asm volatile("cp.async.ca.shared.global [%0], [%1], 16, %2;" ::           \
                             "r"(dst), "l"(src), "r"(sz));                            \
        }                                                                             \
        _Pragma("unroll") for (int p = 0; p < 2; p++) {                               \
            int kr = b_kr0 + p * 16;                                                  \
            const __nv_bfloat16* src =                                                \
                B + (size_t)((kb) + kr) * ldb + col0 + b_cw * 8;                      \
            unsigned int dst = (unsigned int)__cvta_generic_to_shared(                \
                bs_ + kr * B_STRIDE_B + b_cw * 16);                                   \
            asm volatile("cp.async.ca.shared.global [%0], [%1], 16, %2;" ::           \
                             "r"(dst), "l"(src), "r"(16));                            \
        }                                                                             \
        asm volatile("cp.async.commit_group;");                                       \
    }

    ISSUE_CHUNK16(0, 0);
    ISSUE_CHUNK16(1, 32);

    for (int c = 0; c < NC; c++) {
        if (c + 1 < NC) {
            asm volatile("cp.async.wait_group 1;");
        } else {
            asm volatile("cp.async.wait_group 0;");
        }
        __syncthreads();
        if (c + 2 < NC) {
            int nb = (c + 2) % 3;
            ISSUE_CHUNK16(nb, (c + 2) * 32);
        }

        int cb3 = c % 3;
        unsigned int as_base = (unsigned int)__cvta_generic_to_shared(aBuf[cb3]);
        unsigned int bs_base = (unsigned int)__cvta_generic_to_shared(bBuf[cb3]);

#pragma unroll
        for (int ks = 0; ks < 2; ks++) {
            unsigned int af[4][4], bf[2][4];
#pragma unroll
            for (int mt = 0; mt < 4; mt++) {
                unsigned int addr = as_base + a_lm_off + mt * 16 * A_STRIDE_B + ks * 32;
                asm volatile(
                    "ldmatrix.sync.aligned.m8n8.x4.shared.b16 {%0,%1,%2,%3}, [%4];"
                    : "=r"(af[mt][0]), "=r"(af[mt][1]), "=r"(af[mt][2]), "=r"(af[mt][3])
                    : "r"(addr));
            }
#pragma unroll
            for (int ntp = 0; ntp < 2; ntp++) {
                unsigned int addr = bs_base + b_lm_off + ks * 16 * B_STRIDE_B + ntp * 32;
                asm volatile(
                    "ldmatrix.sync.aligned.m8n8.x4.trans.shared.b16 {%0,%1,%2,%3}, [%4];"
                    : "=r"(bf[ntp][0]), "=r"(bf[ntp][1]), "=r"(bf[ntp][2]), "=r"(bf[ntp][3])
                    : "r"(addr));
            }
#pragma unroll
            for (int mt = 0; mt < 4; mt++)
#pragma unroll
                for (int nt = 0; nt < 4; nt++) {
                    int ntp = nt >> 1;
                    int ro = (nt & 1) * 2;
                    asm volatile(
                        "mma.sync.aligned.m16n8k16.row.col.f32.bf16.bf16.f32 "
                        "{%0,%1,%2,%3}, {%4,%5,%6,%7}, {%8,%9}, {%0,%1,%2,%3};"
                        : "+f"(acc[mt][nt][0]), "+f"(acc[mt][nt][1]),
                          "+f"(acc[mt][nt][2]), "+f"(acc[mt][nt][3])
                        : "r"(af[mt][0]), "r"(af[mt][1]), "r"(af[mt][2]),
                          "r"(af[mt][3]), "r"(bf[ntp][ro]), "r"(bf[ntp][ro + 1]));
                }
        }
    }

    // epilogue
    float s1 = 0.f, s2 = 0.f;
#pragma unroll
    for (int mt = 0; mt < 4; mt++) {
        int r0 = row0 + wm + mt * 16 + g;
        int r1 = r0 + 8;
#pragma unroll
        for (int nt = 0; nt < 4; nt++) {
            int cb = col0 + wn + nt * 8 + cc * 2;
            float b0 = bias[cb], b1 = bias[cb + 1];
            float v00 = acc[mt][nt][0] + b0, v01 = acc[mt][nt][1] + b1;
            float v10 = acc[mt][nt][2] + b0, v11 = acc[mt][nt][3] + b1;
            int co = cb - cOff;
            if (addC) {
                if (r0 < M) {
                    float2 a0 = *(const float2*)&addC[(size_t)r0 * 256 + co];
                    v00 += a0.x; v01 += a0.y;
                }
                if (r1 < M) {
                    float2 a1 = *(const float2*)&addC[(size_t)r1 * 256 + co];
                    v10 += a1.x; v11 += a1.y;
                }
            }
            if (relu) {
                v00 = fmaxf(v00, 0.f); v01 = fmaxf(v01, 0.f);
                v10 = fmaxf(v10, 0.f); v11 = fmaxf(v11, 0.f);
            }
            if (r0 < M) {
                if (Cf) *(float2*)&Cf[(size_t)r0 * 256 + co] = make_float2(v00, v01);
                if (Cht) {
                    unsigned int pk;
                    asm("cvt.rn.bf16x2.f32 %0, %1, %2;" : "=r"(pk) : "f"(v01), "f"(v00));
                    *(unsigned int*)&Cht[(size_t)r0 * 256 + co] = pk;
                }
                s1 += v00 + v01;
                s2 += v00 * v00 + v01 * v01;
            }
            if (r1 < M) {
                if (Cf) *(float2*)&Cf[(size_t)r1 * 256 + co] = make_float2(v10, v11);
                if (Cht) {
                    unsigned int pk;
                    asm("cvt.rn.bf16x2.f32 %0, %1, %2;" : "=r"(pk) : "f"(v11), "f"(v10));
                    *(unsigned int*)&Cht[(size_t)r1 * 256 + co] = pk;
                }
                s1 += v10 + v11;
                s2 += v10 * v10 + v11 * v11;
            }
        }
    }
    if (red) {
        __shared__ float sh1[8], sh2[8];
#pragma unroll
        for (int o = 16; o; o >>= 1) {
            s1 += __shfl_xor_sync(0xffffffffu, s1, o);
            s2 += __shfl_xor_sync(0xffffffffu, s2, o);
        }
        if (lane == 0) { sh1[w] = s1; sh2[w] = s2; }
        __syncthreads();
        if (tid == 0) {
            float A_ = 0.f, B_ = 0.f;
#pragma unroll
            for (int i = 0; i < 8; i++) { A_ += sh1[i]; B_ += sh2[i]; }
            int part = blockIdx.y * gridDim.x + blockIdx.x;
            g_red[2 * part] = A_;
            g_red[2 * part + 1] = B_;
        }
    }
}

// ---------------- GATv2: warp/node, dual-chain online softmax ---------------
__device__ __forceinline__ void bf8_to_f(uint4 u, float* v) {
    const __nv_bfloat162* p = (const __nv_bfloat162*)&u;
#pragma unroll
    for (int i = 0; i < 4; i++) {
        float2 f = __bfloat1622float2(p[i]);
        v[2 * i] = f.x;
        v[2 * i + 1] = f.y;
    }
}

__global__ void __launch_bounds__(256)
k_gat(const __nv_bfloat16* __restrict__ hl, const __nv_bfloat16* __restrict__ hr,
      const float* __restrict__ h, const float* __restrict__ att,
      const float* __restrict__ gbias, float* __restrict__ y) {
    int lane = threadIdx.x & 31;
    int wwid = threadIdx.x >> 5;
    int n = blockIdx.x * 8 + wwid;          // NN % 8 == 0: no tail
    int jb = lane * 8;

    float hrv[8], attv[8];
    bf8_to_f(*(const uint4*)&hr[(size_t)n * 256 + jb], hrv);
    *(float4*)&attv[0] = *(const float4*)&att[jb];
    *(float4*)&attv[4] = *(const float4*)&att[jb + 4];

    float accA[8], accB[8];
#pragma unroll
    for (int i = 0; i < 8; i++) { accA[i] = 0.f; accB[i] = 0.f; }
    float mA = -INFINITY, zA = 0.f, mB = -INFINITY, zB = 0.f;

    int k0 = g_off[n], k1 = g_off[n + 1];
    uint4 c0 = *(const uint4*)&hl[(size_t)g_csr_src[k0] * 256 + jb];
    uint4 c1 = c0;
    if (k0 + 1 < k1) c1 = *(const uint4*)&hl[(size_t)g_csr_src[k0 + 1] * 256 + jb];

    for (int k = k0; k < k1; k += 2) {
        uint4 n0 = c0, n1 = c1;
        if (k + 2 < k1) n0 = *(const uint4*)&hl[(size_t)g_csr_src[k + 2] * 256 + jb];
        if (k + 3 < k1) n1 = *(const uint4*)&hl[(size_t)g_csr_src[k + 3] * 256 + jb];

        float vA[8], vB[8];
        bf8_to_f(c0, vA);
        bf8_to_f(c1, vB);
        float pA = 0.f, pB = 0.f;
#pragma unroll
        for (int i = 0; i < 8; i++) {
            float sA = vA[i] + hrv[i];
            sA = sA > 0.f ? sA : 0.2f * sA;
            pA = fmaf(sA, attv[i], pA);
            float sB = vB[i] + hrv[i];
            sB = sB > 0.f ? sB : 0.2f * sB;
            pB = fmaf(sB, attv[i], pB);
        }
        pA += __shfl_xor_sync(0xffffffffu, pA, 1);
        pB += __shfl_xor_sync(0xffffffffu, pB, 1);
        pA += __shfl_xor_sync(0xffffffffu, pA, 2);
        pB += __shfl_xor_sync(0xffffffffu, pB, 2);

        {
            float mn = fmaxf(mA, pA);
            float sc = __expf(mA - mn);
            float wg = __expf(pA - mn);
#pragma unroll
            for (int i = 0; i < 8; i++) accA[i] = accA[i] * sc + wg * vA[i];
            zA = zA * sc + wg;
            mA = mn;
        }
        if (k + 1 < k1) {
            float mn = fmaxf(mB, pB);
            float sc = __expf(mB - mn);
            float wg = __expf(pB - mn);
#pragma unroll
            for (int i = 0; i < 8; i++) accB[i] = accB[i] * sc + wg * vB[i];
            zB = zB * sc + wg;
            mB = mn;
        }
        c0 = n0;
        c1 = n1;
    }

    float mn = fmaxf(mA, mB);
    float sA = __expf(mA - mn), sB = __expf(mB - mn);
    float z = zA * sA + zB * sB;
    float invz = 1.f / (z + 1e-16f);

    float gb[8], hh[8], outv[8];
    *(float4*)&gb[0] = *(const float4*)&gbias[jb];
    *(float4*)&gb[4] = *(const float4*)&gbias[jb + 4];
    *(float4*)&hh[0] = *(const float4*)&h[(size_t)n * 256 + jb];
    *(float4*)&hh[4] = *(const float4*)&h[(size_t)n * 256 + jb + 4];
    float s1 = 0.f, s2 = 0.f;
#pragma unroll
    for (int i = 0; i < 8; i++) {
        float o = (accA[i] * sA + accB[i] * sB) * invz + gb[i] + hh[i];
        outv[i] = o;
        s1 += o;
        s2 += o * o;
    }
    *(float4*)&y[(size_t)n * 256 + jb] = *(float4*)&outv[0];
    *(float4*)&y[(size_t)n * 256 + jb + 4] = *(float4*)&outv[4];

#pragma unroll
    for (int o = 16; o; o >>= 1) {
        s1 += __shfl_xor_sync(0xffffffffu, s1, o);
        s2 += __shfl_xor_sync(0xffffffffu, s2, o);
    }
    __shared__ float sh1[8], sh2[8];
    if (lane == 0) { sh1[wwid] = s1; sh2[wwid] = s2; }
    __syncthreads();
    if (threadIdx.x == 0) {
        float A_ = 0.f, B_ = 0.f;
#pragma unroll
        for (int i = 0; i < 8; i++) { A_ += sh1[i]; B_ += sh2[i]; }
        g_red[2 * blockIdx.x] = A_;
        g_red[2 * blockIdx.x + 1] = B_;
    }
}

// ---------------- LN normalize with inlined (block-redundant) finalize ------
// Every block deterministically reduces g_red[0..npart) in the same order,
// so all blocks compute bitwise-identical mu/rsig. float4 elementwise pass.
__global__ void __launch_bounds__(256)
k_ln_norm(const float* __restrict__ in, float* __restrict__ outf,
          __nv_bfloat16* __restrict__ outh,
          const float* __restrict__ wl, const float* __restrict__ bl,
          int npart) {
    __shared__ double sa[256], sb[256];
    int t = threadIdx.x;
    double a = 0.0, b = 0.0;
    for (int i = t; i < npart; i += 256) {
        a += (double)g_red[2 * i];
        b += (double)g_red[2 * i + 1];
    }
    sa[t] = a;
    sb[t] = b;
    __syncthreads();
    for (int o = 128; o; o >>= 1) {
        if (t < o) { sa[t] += sa[t + o]; sb[t] += sb[t + o]; }
        __syncthreads();
    }
    double inv = 1.0 / ((double)NN * 256.0);
    double mud = sa[0] * inv;
    double var = sb[0] * inv - mud * mud;
    float mu = (float)mud;
    float rs = (float)(1.0 / sqrt(var + 1e-5));

    size_t total = (size_t)NN * 64;  // float4 groups
    for (size_t i = (size_t)blockIdx.x * blockDim.x + threadIdx.x; i < total;
         i += (size_t)gridDim.x * blockDim.x) {
        size_t e = i * 4;
        int c = (int)(e & 255);
        float4 v = *(const float4*)&in[e];
        float o0 = (v.x - mu) * rs * wl[c] + bl[c];
        float o1 = (v.y - mu) * rs * wl[c + 1] + bl[c + 1];
        float o2 = (v.z - mu) * rs * wl[c + 2] + bl[c + 2];
        float o3 = (v.w - mu) * rs * wl[c + 3] + bl[c + 3];
        if (outf) *(float4*)&outf[e] = make_float4(o0, o1, o2, o3);
        if (outh) {
            unsigned int pk0, pk1;
            asm("cvt.rn.bf16x2.f32 %0, %1, %2;" : "=r"(pk0) : "f"(o1), "f"(o0));
            asm("cvt.rn.bf16x2.f32 %0, %1, %2;" : "=r"(pk1) : "f"(o3), "f"(o2));
            *(uint2*)&outh[e] = make_uint2(pk0, pk1);
        }
    }
}

// ---------------- post2: [N,256] @ [256,32] + b ----------------
__global__ void __launch_bounds__(256)
k_post2(const float* __restrict__ Hin, const float* __restrict__ Wp,
        const float* __restrict__ bp) {
    __shared__ float ws[256 * 32];
    __shared__ float hs[8 * 256];
    int tid = threadIdx.x;
    for (int i = tid; i < 256 * 32; i += 256) ws[i] = Wp[i];
    int row0 = blockIdx.x * 8;
    for (int i = tid; i < 8 * 256; i += 256) {
        int r = row0 + (i >> 8);
        hs[i] = (r < NN) ? Hin[(size_t)r * 256 + (i & 255)] : 0.f;
    }
    __syncthreads();
    int r = tid >> 5, c = tid & 31;
    float acc = 0.f;
#pragma unroll 8
    for (int k = 0; k < 256; k++) acc += hs[r * 256 + k] * ws[k * 32 + c];
    int row = row0 + r;
    if (row < NN) g_hf[(size_t)row * 32 + c] = acc + bp[c];
}

// ---------------- link predictor (2-way ILP) ----------------
__global__ void __launch_bounds__(256)
k_link(const int* __restrict__ li, const float* __restrict__ lw,
       const float* __restrict__ lb, float* __restrict__ out) {
    int lane = threadIdx.x & 31;
    int wid = (blockIdx.x * blockDim.x + threadIdx.x) >> 5;
    int nw = (gridDim.x * blockDim.x) >> 5;
    float w = lw[lane];
    float bb = lb[0];
    for (int e = wid; e < ELINK; e += 2 * nw) {
        int e2 = e + nw;
        int s1i = li[e], d1i = li[ELINK + e];
        float p1 = g_hf[(size_t)s1i * 32 + lane] * g_hf[(size_t)d1i * 32 + lane] * w;
        float p2 = 0.f;
        bool has2 = (e2 < ELINK);
        if (has2) {
            int s2i = li[e2], d2i = li[ELINK + e2];
            p2 = g_hf[(size_t)s2i * 32 + lane] * g_hf[(size_t)d2i * 32 + lane] * w;
        }
#pragma unroll
        for (int o = 16; o; o >>= 1) {
            p1 += __shfl_xor_sync(0xffffffffu, p1, o);
            p2 += __shfl_xor_sync(0xffffffffu, p2, o);
        }
        if (lane == 0) {
            out[e] = 1.f / (1.f + __expf(-(p1 + bb)));
            if (has2) out[e2] = 1.f / (1.f + __expf(-(p2 + bb)));
        }
    }
}

// ---------------- orchestration ----------------
extern "C" void kernel_launch(void* const* d_in, const int* in_sizes, int n_in,
                              void* d_out, int out_size) {
    const float* x = (const float*)d_in[0];
    const float* t = (const float*)d_in[1];
    const int* ei = (const int*)d_in[2];
    const int* li = (const int*)d_in[3];
    const float* te_w = (const float*)d_in[4];
    const float* te_b = (const float*)d_in[5];
    const float* pre1_w = (const float*)d_in[6];
    const float* pre1_b = (const float*)d_in[7];
    const float* pre2_w = (const float*)d_in[8];
    const float* pre2_b = (const float*)d_in[9];
    const float* lin_l = (const float*)d_in[10];
    const float* lin_l_b = (const float*)d_in[11];
    const float* lin_r = (const float*)d_in[12];
    const float* lin_r_b = (const float*)d_in[13];
    const float* att = (const float*)d_in[14];
    const float* gbias = (const float*)d_in[15];
    const float* n1w = (const float*)d_in[16];
    const float* n1b = (const float*)d_in[17];
    const float* d2b = (const float*)d_in[19];
    const float* d3b = (const float*)d_in[21];
    const float* n3w = (const float*)d_in[22];
    const float* n3b = (const float*)d_in[23];
    const float* post1_b = (const float*)d_in[25];
    const float* post2_w = (const float*)d_in[26];
    const float* post2_b = (const float*)d_in[27];
    const float* link_w = (const float*)d_in[28];
    const float* link_b = (const float*)d_in[29];
    float* out = (float*)d_out;
    (void)in_sizes; (void)n_in; (void)out_size;

    float *bA, *bD, *bE, *blin;
    cudaGetSymbolAddress((void**)&bA, g_bufA);
    cudaGetSymbolAddress((void**)&bD, g_bufD);
    cudaGetSymbolAddress((void**)&bE, g_bufE);
    cudaGetSymbolAddress((void**)&blin, g_blin);
    __nv_bfloat16 *xcat16, *bA16, *bB16, *bC16, *bD16, *bE16, *w16;
    cudaGetSymbolAddress((void**)&xcat16, g_xcat16);
    cudaGetSymbolAddress((void**)&bA16, g_bA16);
    cudaGetSymbolAddress((void**)&bB16, g_bB16);
    cudaGetSymbolAddress((void**)&bC16, g_bC16);
    cudaGetSymbolAddress((void**)&bD16, g_bD16);
    cudaGetSymbolAddress((void**)&bE16, g_bE16);
    cudaGetSymbolAddress((void**)&w16, g_w16);

    static int smem_set = 0;
    if (!smem_set) {
        cudaFuncSetAttribute(k_gemm_bf16, cudaFuncAttributeMaxDynamicSharedMemorySize,
                             GEMM_SMEM_BYTES);
        smem_set = 1;
    }

    dim3 gg((NN + 127) / 128, 2);
    dim3 gg4((NN + 127) / 128, 4);
    const int NPART = ((NN + 127) / 128) * 2;
    const int GAT_BLOCKS = NN / 8;  // 6250, exact
#define GEMM(grid_, A_, Woff_, bias_, Cf_, Ch_, Ch2_, addC_, K_, ldb_, relu_, red_) \
    k_gemm_bf16<<<grid_, 256, GEMM_SMEM_BYTES>>>(A_, w16 + (Woff_), bias_, Cf_,     \
                                                 Ch_, Ch2_, addC_, NN, K_, ldb_,    \
                                                 relu_, red_)

    // weight conversion (fused lin layout + fused lin bias)
    k_wconv<<<(W16_TOTAL + 2048 + 255) / 256, 256>>>(
        pre1_w, pre2_w, lin_l, lin_r,
        (const float*)d_in[18], (const float*)d_in[20], (const float*)d_in[24],
        lin_l_b, lin_r_b);

    // time embed + concat (bf16)
    k_te<<<NN, 384>>>(x, t, te_w, te_b);

    // pre MLP  (launch #4 = pre2, the profiled slot)
    GEMM(gg, xcat16, W16_PRE1, pre1_b, (float*)nullptr, bB16,
         (__nv_bfloat16*)nullptr, (const float*)nullptr, 384, 256, 0, 0);
    GEMM(gg, bB16, W16_PRE2, pre2_b, bA, bA16,
         (__nv_bfloat16*)nullptr, (const float*)nullptr, 256, 256, 0, 0);

    // CSR build
    const int SCAN_BLKS = (NN + 1023) / 1024;
    k_init_deg<<<(NN + 255) / 256, 256>>>();
    k_count<<<(EE + 255) / 256, 256>>>(ei);
    k_scan1<<<SCAN_BLKS, 1024>>>();
    k_scan2<<<1, 1>>>(SCAN_BLKS);
    k_scan3<<<SCAN_BLKS, 1024>>>();
    k_fill<<<(ET + 255) / 256, 256>>>(ei);

    for (int l = 0; l < 4; l++) {
        // fused lin_l|lin_r GEMM: [N,256] @ [256,512]
        GEMM(gg4, bA16, W16_LIN + l * 131072, blin + l * 512, (float*)nullptr,
             bB16, bC16, (const float*)nullptr, 256, 512, 0, 0);
        k_gat<<<GAT_BLOCKS, 256>>>(bB16, bC16, bA, att + l * 256,
                                   gbias + l * 256, bD);
        // n1 LN: stats inlined; bf16 output only
        k_ln_norm<<<1024, 256>>>(bD, (float*)nullptr, bD16, n1w + l * 256,
                                 n1b + l * 256, GAT_BLOCKS);
        GEMM(gg, bD16, W16_D2 + l * 65536, d2b + l * 256, bE, bE16,
             (__nv_bfloat16*)nullptr, (const float*)nullptr, 256, 256, 1, 0);
        // d3 GEMM with fused residual add (h2 + h3) and LN partials
        GEMM(gg, bE16, W16_D3 + l * 65536, d3b + l * 256, bD, (__nv_bfloat16*)nullptr,
             (__nv_bfloat16*)nullptr, bE, 256, 256, 0, 1);
        // n3 LN: fp32 output only needed when a next layer's gat reads it
        k_ln_norm<<<1024, 256>>>(bD, (l == 3) ? (float*)nullptr : bA, bA16,
                                 n3w + l * 256, n3b + l * 256, NPART);
    }

    // post MLP
    GEMM(gg, bA16, W16_POST1, post1_b, bD, (__nv_bfloat16*)nullptr,
         (__nv_bfloat16*)nullptr, (const float*)nullptr, 256, 256, 0, 0);
    k_post2<<<(NN + 7) / 8, 256>>>(bD, post2_w, post2_b);

    // link prediction
    k_link<<<4096, 256>>>(li, link_w, link_b, out);
}

// round 15
// speedup vs baseline: 1.0175x; 1.0175x over previous
#include <cuda_runtime.h>
#include <cuda_bf16.h>
#include <math.h>
#include <stdint.h>

#define NN 50000
#define EE 800000
#define ET 850000      // EE + NN self loops
#define ELINK 1000000
#define PI_2 1.57079632679489662f

// ---------------- device scratch (allocation-free contract) ----------------
__device__ float g_bufA[(size_t)NN * 256];  // h (fp32 trunk)
__device__ float g_bufD[(size_t)NN * 256];  // d3 out (pre-n3)
__device__ float g_bufE[(size_t)NN * 256];  // h2
__device__ float g_hf[(size_t)NN * 32];

__device__ __nv_bfloat16 g_xcat16[(size_t)NN * 384];
__device__ __nv_bfloat16 g_bA16[(size_t)NN * 256];
__device__ __nv_bfloat16 g_bB16[(size_t)NN * 256];  // hl / pre1-temp
__device__ __nv_bfloat16 g_bC16[(size_t)NN * 256];  // hr
__device__ __nv_bfloat16 g_bD16[(size_t)NN * 256];  // y (gat out, pre-n1)
__device__ __nv_bfloat16 g_bE16[(size_t)NN * 256];  // h2

// bf16 weight arena. LIN region holds per-layer fused [K=256, 512] matrices.
#define W16_PRE1 0
#define W16_PRE2 98304
#define W16_LIN  163840
#define W16_D2   688128
#define W16_D3   950272
#define W16_POST1 1212416
#define W16_TOTAL 1277952
__device__ __nv_bfloat16 g_w16[W16_TOTAL];
__device__ float g_blin[4 * 512];   // fused lin bias per layer

// n1-LN folded d2 weights (per current layer)
__device__ __nv_bfloat16 g_wd2s[65536];
__device__ float g_bd2s[256];

__device__ int g_deg[NN];
__device__ int g_off[NN + 1];
__device__ int g_pos[NN];
__device__ int g_csr_src[ET];
__device__ int g_bsum[64];
__device__ float g_red[131072];
__device__ float g_stats[2];   // mu, rsig

// ---------------- weight conversion fp32 -> bf16 (+ fused lin layout) -------
__global__ void k_wconv(const float* p1, const float* p2, const float* ll,
                        const float* lr, const float* d2, const float* d3,
                        const float* po1, const float* llb, const float* lrb) {
    int i = blockIdx.x * blockDim.x + threadIdx.x;
    if (i >= W16_TOTAL + 2048) return;
    if (i >= W16_TOTAL) {
        int j = i - W16_TOTAL;
        int layer = j >> 9, c = j & 511;
        g_blin[j] = (c < 256) ? llb[layer * 256 + c] : lrb[layer * 256 + (c - 256)];
        return;
    }
    float v;
    if (i < W16_PRE2) v = p1[i - W16_PRE1];
    else if (i < W16_LIN) v = p2[i - W16_PRE2];
    else if (i < W16_D2) {
        int l = i - W16_LIN;
        int layer = l >> 17;
        int lm = l & 131071;
        int k = lm >> 9;
        int c = lm & 511;
        const float* src = (c < 256) ? ll : lr;
        v = src[layer * 65536 + k * 256 + (c & 255)];
    }
    else if (i < W16_D3) v = d2[i - W16_D2];
    else if (i < W16_POST1) v = d3[i - W16_D3];
    else v = po1[i - W16_POST1];
    g_w16[i] = __float2bfloat16(v);
}

// ---------------- CSR build ----------------
__global__ void k_init_deg() {
    int i = blockIdx.x * blockDim.x + threadIdx.x;
    if (i < NN) g_deg[i] = 1;  // self loop
}

__global__ void k_count(const int* __restrict__ ei) {
    int e = blockIdx.x * blockDim.x + threadIdx.x;
    if (e < EE) atomicAdd(&g_deg[ei[EE + e]], 1);
}

__global__ void k_scan1() {
    int b = blockIdx.x, t = threadIdx.x;
    int i = b * 1024 + t;
    int d = (i < NN) ? g_deg[i] : 0;
    int lane = t & 31, wid = t >> 5;
    int v = d;
#pragma unroll
    for (int o = 1; o < 32; o <<= 1) {
        int u = __shfl_up_sync(0xffffffffu, v, o);
        if (lane >= o) v += u;
    }
    __shared__ int ws[32];
    if (lane == 31) ws[wid] = v;
    __syncthreads();
    if (wid == 0) {
        int w = ws[lane];
#pragma unroll
        for (int o = 1; o < 32; o <<= 1) {
            int u = __shfl_up_sync(0xffffffffu, w, o);
            if (lane >= o) w += u;
        }
        ws[lane] = w;
    }
    __syncthreads();
    int incl = v + (wid ? ws[wid - 1] : 0);
    if (i < NN) g_off[i] = incl - d;
    if (t == 1023) g_bsum[b] = incl;
}

__global__ void k_scan2(int nblk) {
    int run = 0;
    for (int i = 0; i < nblk; i++) {
        int d = g_bsum[i];
        g_bsum[i] = run;
        run += d;
    }
}

__global__ void k_scan3() {
    int b = blockIdx.x, t = threadIdx.x;
    int i = b * 1024 + t;
    if (i < NN) {
        int off = g_off[i] + g_bsum[b];
        g_off[i] = off;
        g_pos[i] = off;
    }
    if (i == 0) g_off[NN] = ET;
}

__global__ void k_fill(const int* __restrict__ ei) {
    int i = blockIdx.x * blockDim.x + threadIdx.x;
    if (i < EE) {
        int s = ei[i];
        int d = ei[EE + i];
        int p = atomicAdd(&g_pos[d], 1);
        g_csr_src[p] = s;
    } else if (i < ET) {
        int n = i - EE;
        int p = atomicAdd(&g_pos[n], 1);
        g_csr_src[p] = n;
    }
}

// ---------------- time embedding + concat (bf16 out) ----------------
__global__ void k_te(const float* __restrict__ x, const float* __restrict__ t,
                     const float* __restrict__ tw, const float* __restrict__ tb) {
    int n = blockIdx.x;
    int j = threadIdx.x;
    if (j < 128) {
        g_xcat16[(size_t)n * 384 + j] = __float2bfloat16(x[(size_t)n * 128 + j]);
    } else {
        int jj = j - 128;
        float a = t[n] * (1.0f / 1000.0f);
        float sa, ca;
        sincosf(a * PI_2, &sa, &ca);
        float v = sa * tw[jj] + ca * tw[256 + jj] + a * tw[512 + jj] + tb[jj];
        v = v / (1.0f + __expf(-v));  // swish
        g_xcat16[(size_t)n * 384 + j] = __float2bfloat16(v);
    }
}

// ---------------- bf16 tensor-core GEMM, 3-stage pipeline (round-8 proven) --
#define A_STRIDE_B 80    // bytes per A smem row (64B data + 16B pad)
#define B_STRIDE_B 272   // bytes per B smem row (256B data + 16B pad)
#define A_BYTES (128 * A_STRIDE_B)   // 10240
#define B_BYTES (32 * B_STRIDE_B)    // 8704
#define STAGE_BYTES (A_BYTES + B_BYTES)
#define GEMM_SMEM_BYTES (3 * STAGE_BYTES)  // 56832

__global__ void __launch_bounds__(256, 2)
k_gemm_bf16(const __nv_bfloat16* __restrict__ A, const __nv_bfloat16* __restrict__ B,
            const float* __restrict__ bias, float* __restrict__ Cf,
            __nv_bfloat16* __restrict__ Ch, __nv_bfloat16* __restrict__ Ch2,
            const float* __restrict__ addC, int M, int K, int ldb,
            int relu, int red) {
    extern __shared__ char sm[];
    char* aBuf[3] = {sm, sm + STAGE_BYTES, sm + 2 * STAGE_BYTES};
    char* bBuf[3] = {sm + A_BYTES, sm + STAGE_BYTES + A_BYTES,
                     sm + 2 * STAGE_BYTES + A_BYTES};

    int tid = threadIdx.x;
    int lane = tid & 31;
    int w = tid >> 5;
    int wm = (w >> 2) * 64;
    int wn = (w & 3) * 32;
    int g = lane >> 2;
    int cc = lane & 3;
    int row0 = blockIdx.x * 128;
    int col0 = blockIdx.y * 128;

    __nv_bfloat16* Cht = (Ch2 && col0 >= 256) ? Ch2 : Ch;
    int cOff = (Ch2 && col0 >= 256) ? 256 : 0;

    float acc[4][4][4];
#pragma unroll
    for (int mt = 0; mt < 4; mt++)
#pragma unroll
        for (int nt = 0; nt < 4; nt++)
#pragma unroll
            for (int i = 0; i < 4; i++) acc[mt][nt][i] = 0.f;

    int NC = K >> 5;

    int a_row0 = tid >> 2, a_cw = tid & 3;
    int b_kr0 = tid >> 4, b_cw = tid & 15;

    int lm15 = lane & 15;
    int lhi = (lane >> 4) << 4;
    unsigned int a_lm_off = (unsigned int)((wm + lm15) * A_STRIDE_B + lhi);
    unsigned int b_lm_off = (unsigned int)(lm15 * B_STRIDE_B + wn * 2 + lhi);

#define ISSUE_CHUNK16(buf, kb)                                                        \
    {                                                                                 \
        char* as_ = aBuf[buf];                                                        \
        char* bs_ = bBuf[buf];                                                        \
        _Pragma("unroll") for (int p = 0; p < 2; p++) {                               \
            int row = a_row0 + p * 64;                                                \
            const __nv_bfloat16* src = A + (size_t)(row0 + row) * K + (kb) + a_cw * 8;\
            unsigned int dst = (unsigned int)__cvta_generic_to_shared(                \
                as_ + row * A_STRIDE_B + a_cw * 16);                                  \
            int sz = (row0 + row < M) ? 16 : 0;                                       \
            asm volatile("cp.async.ca.shared.global [%0], [%1], 16, %2;" ::           \
                             "r"(dst), "l"(src), "r"(sz));                            \
        }                                                                             \
        _Pragma("unroll") for (int p = 0; p < 2; p++) {                               \
            int kr = b_kr0 + p * 16;                                                  \
            const __nv_bfloat16* src =                                                \
                B + (size_t)((kb) + kr) * ldb + col0 + b_cw * 8;                      \
            unsigned int dst = (unsigned int)__cvta_generic_to_shared(                \
                bs_ + kr * B_STRIDE_B + b_cw * 16);                                   \
            asm volatile("cp.async.ca.shared.global [%0], [%1], 16, %2;" ::           \
                             "r"(dst), "l"(src), "r"(16));                            \
        }                                                                             \
        asm volatile("cp.async.commit_group;");                                       \
    }

    ISSUE_CHUNK16(0, 0);
    ISSUE_CHUNK16(1, 32);

    for (int c = 0; c < NC; c++) {
        if (c + 1 < NC) {
            asm volatile("cp.async.wait_group 1;");
        } else {
            asm volatile("cp.async.wait_group 0;");
        }
        __syncthreads();
        if (c + 2 < NC) {
            int nb = (c + 2) % 3;
            ISSUE_CHUNK16(nb, (c + 2) * 32);
        }

        int cb3 = c % 3;
        unsigned int as_base = (unsigned int)__cvta_generic_to_shared(aBuf[cb3]);
        unsigned int bs_base = (unsigned int)__cvta_generic_to_shared(bBuf[cb3]);

#pragma unroll
        for (int ks = 0; ks < 2; ks++) {
            unsigned int af[4][4], bf[2][4];
#pragma unroll
            for (int mt = 0; mt < 4; mt++) {
                unsigned int addr = as_base + a_lm_off + mt * 16 * A_STRIDE_B + ks * 32;
                asm volatile(
                    "ldmatrix.sync.aligned.m8n8.x4.shared.b16 {%0,%1,%2,%3}, [%4];"
                    : "=r"(af[mt][0]), "=r"(af[mt][1]), "=r"(af[mt][2]), "=r"(af[mt][3])
                    : "r"(addr));
            }
#pragma unroll
            for (int ntp = 0; ntp < 2; ntp++) {
                unsigned int addr = bs_base + b_lm_off + ks * 16 * B_STRIDE_B + ntp * 32;
                asm volatile(
                    "ldmatrix.sync.aligned.m8n8.x4.trans.shared.b16 {%0,%1,%2,%3}, [%4];"
                    : "=r"(bf[ntp][0]), "=r"(bf[ntp][1]), "=r"(bf[ntp][2]), "=r"(bf[ntp][3])
                    : "r"(addr));
            }
#pragma unroll
            for (int mt = 0; mt < 4; mt++)
#pragma unroll
                for (int nt = 0; nt < 4; nt++) {
                    int ntp = nt >> 1;
                    int ro = (nt & 1) * 2;
                    asm volatile(
                        "mma.sync.aligned.m16n8k16.row.col.f32.bf16.bf16.f32 "
                        "{%0,%1,%2,%3}, {%4,%5,%6,%7}, {%8,%9}, {%0,%1,%2,%3};"
                        : "+f"(acc[mt][nt][0]), "+f"(acc[mt][nt][1]),
                          "+f"(acc[mt][nt][2]), "+f"(acc[mt][nt][3])
                        : "r"(af[mt][0]), "r"(af[mt][1]), "r"(af[mt][2]),
                          "r"(af[mt][3]), "r"(bf[ntp][ro]), "r"(bf[ntp][ro + 1]));
                }
        }
    }

    // epilogue
    float s1 = 0.f, s2 = 0.f;
#pragma unroll
    for (int mt = 0; mt < 4; mt++) {
        int r0 = row0 + wm + mt * 16 + g;
        int r1 = r0 + 8;
#pragma unroll
        for (int nt = 0; nt < 4; nt++) {
            int cb = col0 + wn + nt * 8 + cc * 2;
            float b0 = bias[cb], b1 = bias[cb + 1];
            float v00 = acc[mt][nt][0] + b0, v01 = acc[mt][nt][1] + b1;
            float v10 = acc[mt][nt][2] + b0, v11 = acc[mt][nt][3] + b1;
            int co = cb - cOff;
            if (addC) {
                if (r0 < M) {
                    float2 a0 = *(const float2*)&addC[(size_t)r0 * 256 + co];
                    v00 += a0.x; v01 += a0.y;
                }
                if (r1 < M) {
                    float2 a1 = *(const float2*)&addC[(size_t)r1 * 256 + co];
                    v10 += a1.x; v11 += a1.y;
                }
            }
            if (relu) {
                v00 = fmaxf(v00, 0.f); v01 = fmaxf(v01, 0.f);
                v10 = fmaxf(v10, 0.f); v11 = fmaxf(v11, 0.f);
            }
            if (r0 < M) {
                if (Cf) *(float2*)&Cf[(size_t)r0 * 256 + co] = make_float2(v00, v01);
                if (Cht) {
                    unsigned int pk;
                    asm("cvt.rn.bf16x2.f32 %0, %1, %2;" : "=r"(pk) : "f"(v01), "f"(v00));
                    *(unsigned int*)&Cht[(size_t)r0 * 256 + co] = pk;
                }
                s1 += v00 + v01;
                s2 += v00 * v00 + v01 * v01;
            }
            if (r1 < M) {
                if (Cf) *(float2*)&Cf[(size_t)r1 * 256 + co] = make_float2(v10, v11);
                if (Cht) {
                    unsigned int pk;
                    asm("cvt.rn.bf16x2.f32 %0, %1, %2;" : "=r"(pk) : "f"(v11), "f"(v10));
                    *(unsigned int*)&Cht[(size_t)r1 * 256 + co] = pk;
                }
                s1 += v10 + v11;
                s2 += v10 * v10 + v11 * v11;
            }
        }
    }
    if (red) {
        __shared__ float sh1[8], sh2[8];
#pragma unroll
        for (int o = 16; o; o >>= 1) {
            s1 += __shfl_xor_sync(0xffffffffu, s1, o);
            s2 += __shfl_xor_sync(0xffffffffu, s2, o);
        }
        if (lane == 0) { sh1[w] = s1; sh2[w] = s2; }
        __syncthreads();
        if (tid == 0) {
            float A_ = 0.f, B_ = 0.f;
#pragma unroll
            for (int i = 0; i < 8; i++) { A_ += sh1[i]; B_ += sh2[i]; }
            int part = blockIdx.y * gridDim.x + blockIdx.x;
            g_red[2 * part] = A_;
            g_red[2 * part + 1] = B_;
        }
    }
}

// ---------------- GATv2: warp per node, bf16 y output -----------------------
__device__ __forceinline__ void bf8_to_f(uint4 u, float* v) {
    const __nv_bfloat162* p = (const __nv_bfloat162*)&u;
#pragma unroll
    for (int i = 0; i < 4; i++) {
        float2 f = __bfloat1622float2(p[i]);
        v[2 * i] = f.x;
        v[2 * i + 1] = f.y;
    }
}

__global__ void __launch_bounds__(256)
k_gat(const __nv_bfloat16* __restrict__ hl, const __nv_bfloat16* __restrict__ hr,
      const float* __restrict__ h, const float* __restrict__ att,
      const float* __restrict__ gbias, __nv_bfloat16* __restrict__ y16) {
    int lane = threadIdx.x & 31;
    int n = blockIdx.x * 8 + (threadIdx.x >> 5);
    if (n >= NN) return;
    int jb = lane * 8;

    float hrv[8], attv[8];
    bf8_to_f(*(const uint4*)&hr[(size_t)n * 256 + jb], hrv);
    *(float4*)&attv[0] = *(const float4*)&att[jb];
    *(float4*)&attv[4] = *(const float4*)&att[jb + 4];

    float accv[8];
#pragma unroll
    for (int i = 0; i < 8; i++) accv[i] = 0.f;
    float m = -INFINITY, z = 0.f;

    int k0 = g_off[n], k1 = g_off[n + 1];
    uint4 cur = *(const uint4*)&hl[(size_t)g_csr_src[k0] * 256 + jb];

    for (int k = k0; k < k1; k++) {
        uint4 nxt = cur;
        if (k + 1 < k1)
            nxt = *(const uint4*)&hl[(size_t)g_csr_src[k + 1] * 256 + jb];
        float v[8];
        bf8_to_f(cur, v);
        float p = 0.f;
#pragma unroll
        for (int i = 0; i < 8; i++) {
            float sv = v[i] + hrv[i];
            sv = sv > 0.f ? sv : 0.2f * sv;
            p = fmaf(sv, attv[i], p);
        }
        p += __shfl_xor_sync(0xffffffffu, p, 1);
        p += __shfl_xor_sync(0xffffffffu, p, 2);
        float mn = fmaxf(m, p);
        float sc = __expf(m - mn);
        float wgt = __expf(p - mn);
#pragma unroll
        for (int i = 0; i < 8; i++) accv[i] = accv[i] * sc + wgt * v[i];
        z = z * sc + wgt;
        m = mn;
        cur = nxt;
    }

    float invz = 1.f / (z + 1e-16f);
    float gb[8], hh[8], outv[8];
    *(float4*)&gb[0] = *(const float4*)&gbias[jb];
    *(float4*)&gb[4] = *(const float4*)&gbias[jb + 4];
    *(float4*)&hh[0] = *(const float4*)&h[(size_t)n * 256 + jb];
    *(float4*)&hh[4] = *(const float4*)&h[(size_t)n * 256 + jb + 4];
    float s1 = 0.f, s2 = 0.f;
#pragma unroll
    for (int i = 0; i < 8; i++) {
        float o = accv[i] * invz + gb[i] + hh[i];
        outv[i] = o;
        s1 += o;
        s2 += o * o;
    }
    // bf16 y output (n1 LN folded into d2 GEMM)
    unsigned int pk[4];
#pragma unroll
    for (int i = 0; i < 4; i++)
        asm("cvt.rn.bf16x2.f32 %0, %1, %2;"
            : "=r"(pk[i]) : "f"(outv[2 * i + 1]), "f"(outv[2 * i]));
    *(uint4*)&y16[(size_t)n * 256 + jb] = make_uint4(pk[0], pk[1], pk[2], pk[3]);

    // LN partials per node (fp32 exact values)
#pragma unroll
    for (int o = 16; o; o >>= 1) {
        s1 += __shfl_xor_sync(0xffffffffu, s1, o);
        s2 += __shfl_xor_sync(0xffffffffu, s2, o);
    }
    if (lane == 0) {
        g_red[2 * n] = s1;
        g_red[2 * n + 1] = s2;
    }
}

__global__ void k_ln_finalize(int npart) {
    __shared__ double sa[1024], sb[1024];
    int t = threadIdx.x;
    double a = 0.0, b = 0.0;
    for (int i = t; i < npart; i += 1024) {
        a += (double)g_red[2 * i];
        b += (double)g_red[2 * i + 1];
    }
    sa[t] = a;
    sb[t] = b;
    __syncthreads();
    for (int o = 512; o; o >>= 1) {
        if (t < o) { sa[t] += sa[t + o]; sb[t] += sb[t + o]; }
        __syncthreads();
    }
    if (t == 0) {
        double inv = 1.0 / ((double)NN * 256.0);
        double mu = sa[0] * inv;
        double var = sb[0] * inv - mu * mu;
        g_stats[0] = (float)mu;
        g_stats[1] = (float)(1.0 / sqrt(var + 1e-5));
    }
}

// ---- n1-LN fold: W' = (rs*lnw)∘W (rows), bias' = b + (lnb - mu*rs*lnw)@W ----
__global__ void __launch_bounds__(256)
k_scale_d2(const float* __restrict__ Wf, const float* __restrict__ b,
           const float* __restrict__ lnw, const float* __restrict__ lnb) {
    float mu = g_stats[0], rs = g_stats[1];
    int blk = blockIdx.x, t = threadIdx.x;
    if (blk < 256) {
        float alpha = rs * lnw[blk];
        g_wd2s[blk * 256 + t] = __float2bfloat16(alpha * Wf[blk * 256 + t]);
    } else {
        float acc = b[t];
        for (int k = 0; k < 256; k++) {
            float beta = lnb[k] - mu * rs * lnw[k];
            acc = fmaf(beta, Wf[k * 256 + t], acc);
        }
        g_bd2s[t] = acc;
    }
}

__global__ void __launch_bounds__(256)
k_ln_norm(const float* __restrict__ in, float* __restrict__ outf,
          __nv_bfloat16* __restrict__ outh,
          const float* __restrict__ wl, const float* __restrict__ bl) {
    float mu = g_stats[0], rs = g_stats[1];
    size_t total = (size_t)NN * 128;  // pairs
    for (size_t i = (size_t)blockIdx.x * blockDim.x + threadIdx.x; i < total;
         i += (size_t)gridDim.x * blockDim.x) {
        size_t e = i * 2;
        int c = (int)(e & 255);
        float2 v = *(const float2*)&in[e];
        float o0 = (v.x - mu) * rs * wl[c] + bl[c];
        float o1 = (v.y - mu) * rs * wl[c + 1] + bl[c + 1];
        if (outf) *(float2*)&outf[e] = make_float2(o0, o1);
        if (outh) {
            unsigned int pk;
            asm("cvt.rn.bf16x2.f32 %0, %1, %2;" : "=r"(pk) : "f"(o1), "f"(o0));
            *(unsigned int*)&outh[e] = pk;
        }
    }
}

// ---------------- post2: [N,256] @ [256,32] + b ----------------
__global__ void __launch_bounds__(256)
k_post2(const float* __restrict__ Hin, const float* __restrict__ Wp,
        const float* __restrict__ bp) {
    __shared__ float ws[256 * 32];
    __shared__ float hs[8 * 256];
    int tid = threadIdx.x;
    for (int i = tid; i < 256 * 32; i += 256) ws[i] = Wp[i];
    int row0 = blockIdx.x * 8;
    for (int i = tid; i < 8 * 256; i += 256) {
        int r = row0 + (i >> 8);
        hs[i] = (r < NN) ? Hin[(size_t)r * 256 + (i & 255)] : 0.f;
    }
    __syncthreads();
    int r = tid >> 5, c = tid & 31;
    float acc = 0.f;
#pragma unroll 8
    for (int k = 0; k < 256; k++) acc += hs[r * 256 + k] * ws[k * 32 + c];
    int row = row0 + r;
    if (row < NN) g_hf[(size_t)row * 32 + c] = acc + bp[c];
}

// ---------------- link predictor ----------------
__global__ void __launch_bounds__(256)
k_link(const int* __restrict__ li, const float* __restrict__ lw,
       const float* __restrict__ lb, float* __restrict__ out) {
    int lane = threadIdx.x & 31;
    int wid = (blockIdx.x * blockDim.x + threadIdx.x) >> 5;
    int nw = (gridDim.x * blockDim.x) >> 5;
    float w = lw[lane];
    float bb = lb[0];
    for (int e = wid; e < ELINK; e += nw) {
        int s = li[e];
        int d = li[ELINK + e];
        float p = g_hf[(size_t)s * 32 + lane] * g_hf[(size_t)d * 32 + lane] * w;
#pragma unroll
        for (int o = 16; o; o >>= 1) p += __shfl_xor_sync(0xffffffffu, p, o);
        if (lane == 0) out[e] = 1.f / (1.f + __expf(-(p + bb)));
    }
}

// ---------------- orchestration ----------------
extern "C" void kernel_launch(void* const* d_in, const int* in_sizes, int n_in,
                              void* d_out, int out_size) {
    const float* x = (const float*)d_in[0];
    const float* t = (const float*)d_in[1];
    const int* ei = (const int*)d_in[2];
    const int* li = (const int*)d_in[3];
    const float* te_w = (const float*)d_in[4];
    const float* te_b = (const float*)d_in[5];
    const float* pre1_b = (const float*)d_in[7];
    const float* pre2_b = (const float*)d_in[9];
    const float* lin_l = (const float*)d_in[10];
    const float* lin_l_b = (const float*)d_in[11];
    const float* lin_r = (const float*)d_in[12];
    const float* lin_r_b = (const float*)d_in[13];
    const float* att = (const float*)d_in[14];
    const float* gbias = (const float*)d_in[15];
    const float* n1w = (const float*)d_in[16];
    const float* n1b = (const float*)d_in[17];
    const float* d2w_f = (const float*)d_in[18];
    const float* d2b = (const float*)d_in[19];
    const float* d3b = (const float*)d_in[21];
    const float* n3w = (const float*)d_in[22];
    const float* n3b = (const float*)d_in[23];
    const float* post1_b = (const float*)d_in[25];
    const float* post2_w = (const float*)d_in[26];
    const float* post2_b = (const float*)d_in[27];
    const float* link_w = (const float*)d_in[28];
    const float* link_b = (const float*)d_in[29];
    float* out = (float*)d_out;
    (void)in_sizes; (void)n_in; (void)out_size;

    float *bA, *bD, *bE, *blin, *bd2s;
    cudaGetSymbolAddress((void**)&bA, g_bufA);
    cudaGetSymbolAddress((void**)&bD, g_bufD);
    cudaGetSymbolAddress((void**)&bE, g_bufE);
    cudaGetSymbolAddress((void**)&blin, g_blin);
    cudaGetSymbolAddress((void**)&bd2s, g_bd2s);
    __nv_bfloat16 *xcat16, *bA16, *bB16, *bC16, *bD16, *bE16, *w16, *wd2s;
    cudaGetSymbolAddress((void**)&xcat16, g_xcat16);
    cudaGetSymbolAddress((void**)&bA16, g_bA16);
    cudaGetSymbolAddress((void**)&bB16, g_bB16);
    cudaGetSymbolAddress((void**)&bC16, g_bC16);
    cudaGetSymbolAddress((void**)&bD16, g_bD16);
    cudaGetSymbolAddress((void**)&bE16, g_bE16);
    cudaGetSymbolAddress((void**)&w16, g_w16);
    cudaGetSymbolAddress((void**)&wd2s, g_wd2s);

    static int smem_set = 0;
    if (!smem_set) {
        cudaFuncSetAttribute(k_gemm_bf16, cudaFuncAttributeMaxDynamicSharedMemorySize,
                             GEMM_SMEM_BYTES);
        smem_set = 1;
    }

    dim3 gg((NN + 127) / 128, 2);
    dim3 gg4((NN + 127) / 128, 4);
    const int NPART = ((NN + 127) / 128) * 2;
#define GEMM(grid_, A_, B_, bias_, Cf_, Ch_, Ch2_, addC_, K_, ldb_, relu_, red_)    \
    k_gemm_bf16<<<grid_, 256, GEMM_SMEM_BYTES>>>(A_, B_, bias_, Cf_, Ch_, Ch2_,     \
                                                 addC_, NN, K_, ldb_, relu_, red_)

    // weight conversion (fused lin layout + fused lin bias)
    k_wconv<<<(W16_TOTAL + 2048 + 255) / 256, 256>>>(
        (const float*)d_in[6], (const float*)d_in[8], lin_l, lin_r,
        d2w_f, (const float*)d_in[20], (const float*)d_in[24],
        lin_l_b, lin_r_b);

    // time embed + concat (bf16)
    k_te<<<NN, 384>>>(x, t, te_w, te_b);

    // pre MLP  (launch #4 = pre2, the profiled slot)
    GEMM(gg, xcat16, w16 + W16_PRE1, pre1_b, (float*)nullptr, bB16,
         (__nv_bfloat16*)nullptr, (const float*)nullptr, 384, 256, 0, 0);
    GEMM(gg, bB16, w16 + W16_PRE2, pre2_b, bA, bA16,
         (__nv_bfloat16*)nullptr, (const float*)nullptr, 256, 256, 0, 0);

    // CSR build
    const int SCAN_BLKS = (NN + 1023) / 1024;
    k_init_deg<<<(NN + 255) / 256, 256>>>();
    k_count<<<(EE + 255) / 256, 256>>>(ei);
    k_scan1<<<SCAN_BLKS, 1024>>>();
    k_scan2<<<1, 1>>>(SCAN_BLKS);
    k_scan3<<<SCAN_BLKS, 1024>>>();
    k_fill<<<(ET + 255) / 256, 256>>>(ei);

    for (int l = 0; l < 4; l++) {
        // fused lin_l|lin_r GEMM: [N,256] @ [256,512]
        GEMM(gg4, bA16, w16 + W16_LIN + l * 131072, blin + l * 512, (float*)nullptr,
             bB16, bC16, (const float*)nullptr, 256, 512, 0, 0);
        // gat: bf16 y out + LN partials
        k_gat<<<(NN + 7) / 8, 256>>>(bB16, bC16, bA, att + l * 256,
                                     gbias + l * 256, bD16);
        k_ln_finalize<<<1, 1024>>>(NN);
        // fold n1 LN into d2 weights/bias (replaces the ln_norm pass)
        k_scale_d2<<<257, 256>>>(d2w_f + (size_t)l * 65536, d2b + l * 256,
                                 n1w + l * 256, n1b + l * 256);
        GEMM(gg, bD16, wd2s, bd2s, bE, bE16,
             (__nv_bfloat16*)nullptr, (const float*)nullptr, 256, 256, 1, 0);
        // d3 GEMM with fused residual add (h2 + h3) and LN partials
        GEMM(gg, bE16, w16 + W16_D3 + l * 65536, d3b + l * 256, bD,
             (__nv_bfloat16*)nullptr, (__nv_bfloat16*)nullptr, bE, 256, 256, 0, 1);
        k_ln_finalize<<<1, 1024>>>(NPART);
        k_ln_norm<<<2048, 256>>>(bD, bA, bA16, n3w + l * 256, n3b + l * 256);
    }

    // post MLP
    GEMM(gg, bA16, w16 + W16_POST1, post1_b, bD, (__nv_bfloat16*)nullptr,
         (__nv_bfloat16*)nullptr, (const float*)nullptr, 256, 256, 0, 0);
    k_post2<<<(NN + 7) / 8, 256>>>(bD, post2_w, post2_b);

    // link prediction
    k_link<<<4096, 256>>>(li, link_w, link_b, out);
}

// round 16
// speedup vs baseline: 1.0252x; 1.0075x over previous
#include <cuda_runtime.h>
#include <cuda_bf16.h>
#include <math.h>
#include <stdint.h>

#define NN 50000
#define EE 800000
#define ET 850000      // EE + NN self loops
#define ELINK 1000000
#define PI_2 1.57079632679489662f

// ---------------- device scratch (allocation-free contract) ----------------
__device__ float g_bufA[(size_t)NN * 256];  // h (fp32 trunk)
__device__ float g_bufD[(size_t)NN * 256];  // y / h1 / scratch
__device__ float g_bufE[(size_t)NN * 256];  // h2
__device__ float g_hf[(size_t)NN * 32];

__device__ __nv_bfloat16 g_xcat16[(size_t)NN * 384];
__device__ __nv_bfloat16 g_bA16[(size_t)NN * 256];
__device__ __nv_bfloat16 g_bB16[(size_t)NN * 256];  // hl / pre1-temp
__device__ __nv_bfloat16 g_bC16[(size_t)NN * 256];  // hr
__device__ __nv_bfloat16 g_bD16[(size_t)NN * 256];  // h1
__device__ __nv_bfloat16 g_bE16[(size_t)NN * 256];  // h2

// bf16 weight arena. LIN region holds per-layer fused [K=256, 512] matrices
// (cols 0-255 = lin_l, cols 256-511 = lin_r).
#define W16_PRE1 0
#define W16_PRE2 98304
#define W16_LIN  163840
#define W16_D2   688128
#define W16_D3   950272
#define W16_POST1 1212416
#define W16_TOTAL 1277952
__device__ __nv_bfloat16 g_w16[W16_TOTAL];
__device__ float g_blin[4 * 512];   // fused lin bias per layer

__device__ int g_deg[NN];
__device__ int g_off[NN + 1];
__device__ int g_pos[NN];
__device__ int g_csr_src[ET];
__device__ int g_bsum[64];
__device__ float g_red[131072];
__device__ float g_stats[2];   // mu, rsig

// ---------------- weight conversion fp32 -> bf16 (+ fused lin layout) -------
__global__ void k_wconv(const float* p1, const float* p2, const float* ll,
                        const float* lr, const float* d2, const float* d3,
                        const float* po1, const float* llb, const float* lrb) {
    int i = blockIdx.x * blockDim.x + threadIdx.x;
    if (i >= W16_TOTAL + 2048) return;
    if (i >= W16_TOTAL) {
        int j = i - W16_TOTAL;
        int layer = j >> 9, c = j & 511;
        g_blin[j] = (c < 256) ? llb[layer * 256 + c] : lrb[layer * 256 + (c - 256)];
        return;
    }
    float v;
    if (i < W16_PRE2) v = p1[i - W16_PRE1];
    else if (i < W16_LIN) v = p2[i - W16_PRE2];
    else if (i < W16_D2) {
        int l = i - W16_LIN;
        int layer = l >> 17;
        int lm = l & 131071;
        int k = lm >> 9;
        int c = lm & 511;
        const float* src = (c < 256) ? ll : lr;
        v = src[layer * 65536 + k * 256 + (c & 255)];
    }
    else if (i < W16_D3) v = d2[i - W16_D2];
    else if (i < W16_POST1) v = d3[i - W16_D3];
    else v = po1[i - W16_POST1];
    g_w16[i] = __float2bfloat16(v);
}

// ---------------- CSR build ----------------
__global__ void k_init_deg() {
    int i = blockIdx.x * blockDim.x + threadIdx.x;
    if (i < NN) g_deg[i] = 1;  // self loop
}

__global__ void k_count(const int* __restrict__ ei) {
    int e = blockIdx.x * blockDim.x + threadIdx.x;
    if (e < EE) atomicAdd(&g_deg[ei[EE + e]], 1);
}

__global__ void k_scan1() {
    int b = blockIdx.x, t = threadIdx.x;
    int i = b * 1024 + t;
    int d = (i < NN) ? g_deg[i] : 0;
    int lane = t & 31, wid = t >> 5;
    int v = d;
#pragma unroll
    for (int o = 1; o < 32; o <<= 1) {
        int u = __shfl_up_sync(0xffffffffu, v, o);
        if (lane >= o) v += u;
    }
    __shared__ int ws[32];
    if (lane == 31) ws[wid] = v;
    __syncthreads();
    if (wid == 0) {
        int w = ws[lane];
#pragma unroll
        for (int o = 1; o < 32; o <<= 1) {
            int u = __shfl_up_sync(0xffffffffu, w, o);
            if (lane >= o) w += u;
        }
        ws[lane] = w;
    }
    __syncthreads();
    int incl = v + (wid ? ws[wid - 1] : 0);
    if (i < NN) g_off[i] = incl - d;
    if (t == 1023) g_bsum[b] = incl;
}

__global__ void k_scan2(int nblk) {
    int run = 0;
    for (int i = 0; i < nblk; i++) {
        int d = g_bsum[i];
        g_bsum[i] = run;
        run += d;
    }
}

__global__ void k_scan3() {
    int b = blockIdx.x, t = threadIdx.x;
    int i = b * 1024 + t;
    if (i < NN) {
        int off = g_off[i] + g_bsum[b];
        g_off[i] = off;
        g_pos[i] = off;
    }
    if (i == 0) g_off[NN] = ET;
}

__global__ void k_fill(const int* __restrict__ ei) {
    int i = blockIdx.x * blockDim.x + threadIdx.x;
    if (i < EE) {
        int s = ei[i];
        int d = ei[EE + i];
        int p = atomicAdd(&g_pos[d], 1);
        g_csr_src[p] = s;
    } else if (i < ET) {
        int n = i - EE;
        int p = atomicAdd(&g_pos[n], 1);
        g_csr_src[p] = n;
    }
}

// ---------------- time embedding + concat (bf16 out) ----------------
__global__ void k_te(const float* __restrict__ x, const float* __restrict__ t,
                     const float* __restrict__ tw, const float* __restrict__ tb) {
    int n = blockIdx.x;
    int j = threadIdx.x;
    if (j < 128) {
        g_xcat16[(size_t)n * 384 + j] = __float2bfloat16(x[(size_t)n * 128 + j]);
    } else {
        int jj = j - 128;
        float a = t[n] * (1.0f / 1000.0f);
        float sa, ca;
        sincosf(a * PI_2, &sa, &ca);
        float v = sa * tw[jj] + ca * tw[256 + jj] + a * tw[512 + jj] + tb[jj];
        v = v / (1.0f + __expf(-v));  // swish
        g_xcat16[(size_t)n * 384 + j] = __float2bfloat16(v);
    }
}

// ---------------- bf16 tensor-core GEMM, 3-stage pipeline (round-8 proven) --
#define A_STRIDE_B 80    // bytes per A smem row (64B data + 16B pad)
#define B_STRIDE_B 272   // bytes per B smem row (256B data + 16B pad)
#define A_BYTES (128 * A_STRIDE_B)   // 10240
#define B_BYTES (32 * B_STRIDE_B)    // 8704
#define STAGE_BYTES (A_BYTES + B_BYTES)
#define GEMM_SMEM_BYTES (3 * STAGE_BYTES)  // 56832

__global__ void __launch_bounds__(256, 2)
k_gemm_bf16(const __nv_bfloat16* __restrict__ A, const __nv_bfloat16* __restrict__ B,
            const float* __restrict__ bias, float* __restrict__ Cf,
            __nv_bfloat16* __restrict__ Ch, __nv_bfloat16* __restrict__ Ch2,
            const float* __restrict__ addC, int M, int K, int ldb,
            int relu, int red) {
    extern __shared__ char sm[];
    char* aBuf[3] = {sm, sm + STAGE_BYTES, sm + 2 * STAGE_BYTES};
    char* bBuf[3] = {sm + A_BYTES, sm + STAGE_BYTES + A_BYTES,
                     sm + 2 * STAGE_BYTES + A_BYTES};

    int tid = threadIdx.x;
    int lane = tid & 31;
    int w = tid >> 5;
    int wm = (w >> 2) * 64;
    int wn = (w & 3) * 32;
    int g = lane >> 2;
    int cc = lane & 3;
    int row0 = blockIdx.x * 128;
    int col0 = blockIdx.y * 128;

    __nv_bfloat16* Cht = (Ch2 && col0 >= 256) ? Ch2 : Ch;
    int cOff = (Ch2 && col0 >= 256) ? 256 : 0;

    float acc[4][4][4];
#pragma unroll
    for (int mt = 0; mt < 4; mt++)
#pragma unroll
        for (int nt = 0; nt < 4; nt++)
#pragma unroll
            for (int i = 0; i < 4; i++) acc[mt][nt][i] = 0.f;

    int NC = K >> 5;

    int a_row0 = tid >> 2, a_cw = tid & 3;
    int b_kr0 = tid >> 4, b_cw = tid & 15;

    int lm15 = lane & 15;
    int lhi = (lane >> 4) << 4;
    unsigned int a_lm_off = (unsigned int)((wm + lm15) * A_STRIDE_B + lhi);
    unsigned int b_lm_off = (unsigned int)(lm15 * B_STRIDE_B + wn * 2 + lhi);

#define ISSUE_CHUNK16(buf, kb)                                                        \
    {                                                                                 \
        char* as_ = aBuf[buf];                                                        \
        char* bs_ = bBuf[buf];                                                        \
        _Pragma("unroll") for (int p = 0; p < 2; p++) {                               \
            int row = a_row0 + p * 64;                                                \
            const __nv_bfloat16* src = A + (size_t)(row0 + row) * K + (kb) + a_cw * 8;\
            unsigned int dst = (unsigned int)__cvta_generic_to_shared(                \
                as_ + row * A_STRIDE_B + a_cw * 16);                                  \
            int sz = (row0 + row < M) ? 16 : 0;                                       \
            asm volatile("cp.async.ca.shared.global [%0], [%1], 16, %2;" ::           \
                             "r"(dst), "l"(src), "r"(sz));                            \
        }                                                                             \
        _Pragma("unroll") for (int p = 0; p < 2; p++) {                               \
            int kr = b_kr0 + p * 16;                                                  \
            const __nv_bfloat16* src =                                                \
                B + (size_t)((kb) + kr) * ldb + col0 + b_cw * 8;                      \
            unsigned int dst = (unsigned int)__cvta_generic_to_shared(                \
                bs_ + kr * B_STRIDE_B + b_cw * 16);                                   \
            asm volatile("cp.async.ca.shared.global [%0], [%1], 16, %2;" ::           \
                             "r"(dst), "l"(src), "r"(16));                            \
        }                                                                             \
        asm volatile("cp.async.commit_group;");                                       \
    }

    ISSUE_CHUNK16(0, 0);
    ISSUE_CHUNK16(1, 32);

    for (int c = 0; c < NC; c++) {
        if (c + 1 < NC) {
            asm volatile("cp.async.wait_group 1;");
        } else {
            asm volatile("cp.async.wait_group 0;");
        }
        __syncthreads();
        if (c + 2 < NC) {
            int nb = (c + 2) % 3;
            ISSUE_CHUNK16(nb, (c + 2) * 32);
        }

        int cb3 = c % 3;
        unsigned int as_base = (unsigned int)__cvta_generic_to_shared(aBuf[cb3]);
        unsigned int bs_base = (unsigned int)__cvta_generic_to_shared(bBuf[cb3]);

#pragma unroll
        for (int ks = 0; ks < 2; ks++) {
            unsigned int af[4][4], bf[2][4];
#pragma unroll
            for (int mt = 0; mt < 4; mt++) {
                unsigned int addr = as_base + a_lm_off + mt * 16 * A_STRIDE_B + ks * 32;
                asm volatile(
                    "ldmatrix.sync.aligned.m8n8.x4.shared.b16 {%0,%1,%2,%3}, [%4];"
                    : "=r"(af[mt][0]), "=r"(af[mt][1]), "=r"(af[mt][2]), "=r"(af[mt][3])
                    : "r"(addr));
            }
#pragma unroll
            for (int ntp = 0; ntp < 2; ntp++) {
                unsigned int addr = bs_base + b_lm_off + ks * 16 * B_STRIDE_B + ntp * 32;
                asm volatile(
                    "ldmatrix.sync.aligned.m8n8.x4.trans.shared.b16 {%0,%1,%2,%3}, [%4];"
                    : "=r"(bf[ntp][0]), "=r"(bf[ntp][1]), "=r"(bf[ntp][2]), "=r"(bf[ntp][3])
                    : "r"(addr));
            }
#pragma unroll
            for (int mt = 0; mt < 4; mt++)
#pragma unroll
                for (int nt = 0; nt < 4; nt++) {
                    int ntp = nt >> 1;
                    int ro = (nt & 1) * 2;
                    asm volatile(
                        "mma.sync.aligned.m16n8k16.row.col.f32.bf16.bf16.f32 "
                        "{%0,%1,%2,%3}, {%4,%5,%6,%7}, {%8,%9}, {%0,%1,%2,%3};"
                        : "+f"(acc[mt][nt][0]), "+f"(acc[mt][nt][1]),
                          "+f"(acc[mt][nt][2]), "+f"(acc[mt][nt][3])
                        : "r"(af[mt][0]), "r"(af[mt][1]), "r"(af[mt][2]),
                          "r"(af[mt][3]), "r"(bf[ntp][ro]), "r"(bf[ntp][ro + 1]));
                }
        }
    }

    // epilogue
    float s1 = 0.f, s2 = 0.f;
#pragma unroll
    for (int mt = 0; mt < 4; mt++) {
        int r0 = row0 + wm + mt * 16 + g;
        int r1 = r0 + 8;
#pragma unroll
        for (int nt = 0; nt < 4; nt++) {
            int cb = col0 + wn + nt * 8 + cc * 2;
            float b0 = bias[cb], b1 = bias[cb + 1];
            float v00 = acc[mt][nt][0] + b0, v01 = acc[mt][nt][1] + b1;
            float v10 = acc[mt][nt][2] + b0, v11 = acc[mt][nt][3] + b1;
            int co = cb - cOff;
            if (addC) {
                if (r0 < M) {
                    float2 a0 = *(const float2*)&addC[(size_t)r0 * 256 + co];
                    v00 += a0.x; v01 += a0.y;
                }
                if (r1 < M) {
                    float2 a1 = *(const float2*)&addC[(size_t)r1 * 256 + co];
                    v10 += a1.x; v11 += a1.y;
                }
            }
            if (relu) {
                v00 = fmaxf(v00, 0.f); v01 = fmaxf(v01, 0.f);
                v10 = fmaxf(v10, 0.f); v11 = fmaxf(v11, 0.f);
            }
            if (r0 < M) {
                if (Cf) *(float2*)&Cf[(size_t)r0 * 256 + co] = make_float2(v00, v01);
                if (Cht) {
                    unsigned int pk;
                    asm("cvt.rn.bf16x2.f32 %0, %1, %2;" : "=r"(pk) : "f"(v01), "f"(v00));
                    *(unsigned int*)&Cht[(size_t)r0 * 256 + co] = pk;
                }
                s1 += v00 + v01;
                s2 += v00 * v00 + v01 * v01;
            }
            if (r1 < M) {
                if (Cf) *(float2*)&Cf[(size_t)r1 * 256 + co] = make_float2(v10, v11);
                if (Cht) {
                    unsigned int pk;
                    asm("cvt.rn.bf16x2.f32 %0, %1, %2;" : "=r"(pk) : "f"(v11), "f"(v10));
                    *(unsigned int*)&Cht[(size_t)r1 * 256 + co] = pk;
                }
                s1 += v10 + v11;
                s2 += v10 * v10 + v11 * v11;
            }
        }
    }
    if (red) {
        __shared__ float sh1[8], sh2[8];
#pragma unroll
        for (int o = 16; o; o >>= 1) {
            s1 += __shfl_xor_sync(0xffffffffu, s1, o);
            s2 += __shfl_xor_sync(0xffffffffu, s2, o);
        }
        if (lane == 0) { sh1[w] = s1; sh2[w] = s2; }
        __syncthreads();
        if (tid == 0) {
            float A_ = 0.f, B_ = 0.f;
#pragma unroll
            for (int i = 0; i < 8; i++) { A_ += sh1[i]; B_ += sh2[i]; }
            int part = blockIdx.y * gridDim.x + blockIdx.x;
            g_red[2 * part] = A_;
            g_red[2 * part + 1] = B_;
        }
    }
}

// ---------------- GATv2: warp per node (round-8 version) --------------------
__device__ __forceinline__ void bf8_to_f(uint4 u, float* v) {
    const __nv_bfloat162* p = (const __nv_bfloat162*)&u;
#pragma unroll
    for (int i = 0; i < 4; i++) {
        float2 f = __bfloat1622float2(p[i]);
        v[2 * i] = f.x;
        v[2 * i + 1] = f.y;
    }
}

__global__ void __launch_bounds__(256)
k_gat(const __nv_bfloat16* __restrict__ hl, const __nv_bfloat16* __restrict__ hr,
      const float* __restrict__ h, const float* __restrict__ att,
      const float* __restrict__ gbias, float* __restrict__ y) {
    int lane = threadIdx.x & 31;
    int n = blockIdx.x * 8 + (threadIdx.x >> 5);
    if (n >= NN) return;
    int jb = lane * 8;

    float hrv[8], attv[8];
    bf8_to_f(*(const uint4*)&hr[(size_t)n * 256 + jb], hrv);
    *(float4*)&attv[0] = *(const float4*)&att[jb];
    *(float4*)&attv[4] = *(const float4*)&att[jb + 4];

    float accv[8];
#pragma unroll
    for (int i = 0; i < 8; i++) accv[i] = 0.f;
    float m = -INFINITY, z = 0.f;

    int k0 = g_off[n], k1 = g_off[n + 1];
    uint4 cur = *(const uint4*)&hl[(size_t)g_csr_src[k0] * 256 + jb];

    for (int k = k0; k < k1; k++) {
        uint4 nxt = cur;
        if (k + 1 < k1)
            nxt = *(const uint4*)&hl[(size_t)g_csr_src[k + 1] * 256 + jb];
        float v[8];
        bf8_to_f(cur, v);
        float p = 0.f;
#pragma unroll
        for (int i = 0; i < 8; i++) {
            float sv = v[i] + hrv[i];
            sv = sv > 0.f ? sv : 0.2f * sv;
            p = fmaf(sv, attv[i], p);
        }
        p += __shfl_xor_sync(0xffffffffu, p, 1);
        p += __shfl_xor_sync(0xffffffffu, p, 2);
        float mn = fmaxf(m, p);
        float sc = __expf(m - mn);
        float wgt = __expf(p - mn);
#pragma unroll
        for (int i = 0; i < 8; i++) accv[i] = accv[i] * sc + wgt * v[i];
        z = z * sc + wgt;
        m = mn;
        cur = nxt;
    }

    float invz = 1.f / (z + 1e-16f);
    float gb[8], hh[8], outv[8];
    *(float4*)&gb[0] = *(const float4*)&gbias[jb];
    *(float4*)&gb[4] = *(const float4*)&gbias[jb + 4];
    *(float4*)&hh[0] = *(const float4*)&h[(size_t)n * 256 + jb];
    *(float4*)&hh[4] = *(const float4*)&h[(size_t)n * 256 + jb + 4];
    float s1 = 0.f, s2 = 0.f;
#pragma unroll
    for (int i = 0; i < 8; i++) {
        float o = accv[i] * invz + gb[i] + hh[i];
        outv[i] = o;
        s1 += o;
        s2 += o * o;
    }
    *(float4*)&y[(size_t)n * 256 + jb] = *(float4*)&outv[0];
    *(float4*)&y[(size_t)n * 256 + jb + 4] = *(float4*)&outv[4];

#pragma unroll
    for (int o = 16; o; o >>= 1) {
        s1 += __shfl_xor_sync(0xffffffffu, s1, o);
        s2 += __shfl_xor_sync(0xffffffffu, s2, o);
    }
    if (lane == 0) {
        g_red[2 * n] = s1;
        g_red[2 * n + 1] = s2;
    }
}

__global__ void k_ln_finalize(int npart) {
    __shared__ double sa[1024], sb[1024];
    int t = threadIdx.x;
    double a = 0.0, b = 0.0;
    for (int i = t; i < npart; i += 1024) {
        a += (double)g_red[2 * i];
        b += (double)g_red[2 * i + 1];
    }
    sa[t] = a;
    sb[t] = b;
    __syncthreads();
    for (int o = 512; o; o >>= 1) {
        if (t < o) { sa[t] += sa[t + o]; sb[t] += sb[t + o]; }
        __syncthreads();
    }
    if (t == 0) {
        double inv = 1.0 / ((double)NN * 256.0);
        double mu = sa[0] * inv;
        double var = sb[0] * inv - mu * mu;
        g_stats[0] = (float)mu;
        g_stats[1] = (float)(1.0 / sqrt(var + 1e-5));
    }
}

__global__ void __launch_bounds__(256)
k_ln_norm(const float* __restrict__ in, float* __restrict__ outf,
          __nv_bfloat16* __restrict__ outh,
          const float* __restrict__ wl, const float* __restrict__ bl) {
    float mu = g_stats[0], rs = g_stats[1];
    size_t total = (size_t)NN * 128;  // pairs
    for (size_t i = (size_t)blockIdx.x * blockDim.x + threadIdx.x; i < total;
         i += (size_t)gridDim.x * blockDim.x) {
        size_t e = i * 2;
        int c = (int)(e & 255);
        float2 v = *(const float2*)&in[e];
        float o0 = (v.x - mu) * rs * wl[c] + bl[c];
        float o1 = (v.y - mu) * rs * wl[c + 1] + bl[c + 1];
        if (outf) *(float2*)&outf[e] = make_float2(o0, o1);
        if (outh) {
            unsigned int pk;
            asm("cvt.rn.bf16x2.f32 %0, %1, %2;" : "=r"(pk) : "f"(o1), "f"(o0));
            *(unsigned int*)&outh[e] = pk;
        }
    }
}

// ---------------- post2: [N,256] @ [256,32] + b ----------------
__global__ void __launch_bounds__(256)
k_post2(const float* __restrict__ Hin, const float* __restrict__ Wp,
        const float* __restrict__ bp) {
    __shared__ float ws[256 * 32];
    __shared__ float hs[8 * 256];
    int tid = threadIdx.x;
    for (int i = tid; i < 256 * 32; i += 256) ws[i] = Wp[i];
    int row0 = blockIdx.x * 8;
    for (int i = tid; i < 8 * 256; i += 256) {
        int r = row0 + (i >> 8);
        hs[i] = (r < NN) ? Hin[(size_t)r * 256 + (i & 255)] : 0.f;
    }
    __syncthreads();
    int r = tid >> 5, c = tid & 31;
    float acc = 0.f;
#pragma unroll 8
    for (int k = 0; k < 256; k++) acc += hs[r * 256 + k] * ws[k * 32 + c];
    int row = row0 + r;
    if (row < NN) g_hf[(size_t)row * 32 + c] = acc + bp[c];
}

// ---------------- link predictor ----------------
__global__ void __launch_bounds__(256)
k_link(const int* __restrict__ li, const float* __restrict__ lw,
       const float* __restrict__ lb, float* __restrict__ out) {
    int lane = threadIdx.x & 31;
    int wid = (blockIdx.x * blockDim.x + threadIdx.x) >> 5;
    int nw = (gridDim.x * blockDim.x) >> 5;
    float w = lw[lane];
    float bb = lb[0];
    for (int e = wid; e < ELINK; e += nw) {
        int s = li[e];
        int d = li[ELINK + e];
        float p = g_hf[(size_t)s * 32 + lane] * g_hf[(size_t)d * 32 + lane] * w;
#pragma unroll
        for (int o = 16; o; o >>= 1) p += __shfl_xor_sync(0xffffffffu, p, o);
        if (lane == 0) out[e] = 1.f / (1.f + __expf(-(p + bb)));
    }
}

// ---------------- orchestration ----------------
extern "C" void kernel_launch(void* const* d_in, const int* in_sizes, int n_in,
                              void* d_out, int out_size) {
    const float* x = (const float*)d_in[0];
    const float* t = (const float*)d_in[1];
    const int* ei = (const int*)d_in[2];
    const int* li = (const int*)d_in[3];
    const float* te_w = (const float*)d_in[4];
    const float* te_b = (const float*)d_in[5];
    const float* pre1_b = (const float*)d_in[7];
    const float* pre2_b = (const float*)d_in[9];
    const float* lin_l = (const float*)d_in[10];
    const float* lin_l_b = (const float*)d_in[11];
    const float* lin_r = (const float*)d_in[12];
    const float* lin_r_b = (const float*)d_in[13];
    const float* att = (const float*)d_in[14];
    const float* gbias = (const float*)d_in[15];
    const float* n1w = (const float*)d_in[16];
    const float* n1b = (const float*)d_in[17];
    const float* d2b = (const float*)d_in[19];
    const float* d3b = (const float*)d_in[21];
    const float* n3w = (const float*)d_in[22];
    const float* n3b = (const float*)d_in[23];
    const float* post1_b = (const float*)d_in[25];
    const float* post2_w = (const float*)d_in[26];
    const float* post2_b = (const float*)d_in[27];
    const float* link_w = (const float*)d_in[28];
    const float* link_b = (const float*)d_in[29];
    float* out = (float*)d_out;
    (void)in_sizes; (void)n_in; (void)out_size;

    float *bA, *bD, *bE, *blin;
    cudaGetSymbolAddress((void**)&bA, g_bufA);
    cudaGetSymbolAddress((void**)&bD, g_bufD);
    cudaGetSymbolAddress((void**)&bE, g_bufE);
    cudaGetSymbolAddress((void**)&blin, g_blin);
    __nv_bfloat16 *xcat16, *bA16, *bB16, *bC16, *bD16, *bE16, *w16;
    cudaGetSymbolAddress((void**)&xcat16, g_xcat16);
    cudaGetSymbolAddress((void**)&bA16, g_bA16);
    cudaGetSymbolAddress((void**)&bB16, g_bB16);
    cudaGetSymbolAddress((void**)&bC16, g_bC16);
    cudaGetSymbolAddress((void**)&bD16, g_bD16);
    cudaGetSymbolAddress((void**)&bE16, g_bE16);
    cudaGetSymbolAddress((void**)&w16, g_w16);

    static int inited = 0;
    static cudaStream_t s2;
    static cudaEvent_t evFork, evJoin;
    if (!inited) {
        cudaFuncSetAttribute(k_gemm_bf16, cudaFuncAttributeMaxDynamicSharedMemorySize,
                             GEMM_SMEM_BYTES);
        cudaStreamCreateWithFlags(&s2, cudaStreamNonBlocking);
        cudaEventCreateWithFlags(&evFork, cudaEventDisableTiming);
        cudaEventCreateWithFlags(&evJoin, cudaEventDisableTiming);
        inited = 1;
    }

    dim3 gg((NN + 127) / 128, 2);
    dim3 gg4((NN + 127) / 128, 4);
    const int NPART = ((NN + 127) / 128) * 2;
#define GEMM(grid_, A_, Woff_, bias_, Cf_, Ch_, Ch2_, addC_, K_, ldb_, relu_, red_) \
    k_gemm_bf16<<<grid_, 256, GEMM_SMEM_BYTES>>>(A_, w16 + (Woff_), bias_, Cf_,     \
                                                 Ch_, Ch2_, addC_, NN, K_, ldb_,    \
                                                 relu_, red_)

    // ---- fork: CSR build runs on s2, overlapping wconv/te/pre-MLP/lin0 ----
    cudaEventRecord(evFork, 0);
    cudaStreamWaitEvent(s2, evFork, 0);
    {
        const int SCAN_BLKS = (NN + 1023) / 1024;
        k_init_deg<<<(NN + 255) / 256, 256, 0, s2>>>();
        k_count<<<(EE + 255) / 256, 256, 0, s2>>>(ei);
        k_scan1<<<SCAN_BLKS, 1024, 0, s2>>>();
        k_scan2<<<1, 1, 0, s2>>>(SCAN_BLKS);
        k_scan3<<<SCAN_BLKS, 1024, 0, s2>>>();
        k_fill<<<(ET + 255) / 256, 256, 0, s2>>>(ei);
        cudaEventRecord(evJoin, s2);
    }

    // main stream: weight conversion + embed + pre MLP
    k_wconv<<<(W16_TOTAL + 2048 + 255) / 256, 256>>>(
        (const float*)d_in[6], (const float*)d_in[8], lin_l, lin_r,
        (const float*)d_in[18], (const float*)d_in[20], (const float*)d_in[24],
        lin_l_b, lin_r_b);
    k_te<<<NN, 384>>>(x, t, te_w, te_b);
    GEMM(gg, xcat16, W16_PRE1, pre1_b, (float*)nullptr, bB16,
         (__nv_bfloat16*)nullptr, (const float*)nullptr, 384, 256, 0, 0);
    GEMM(gg, bB16, W16_PRE2, pre2_b, bA, bA16,
         (__nv_bfloat16*)nullptr, (const float*)nullptr, 256, 256, 0, 0);

    for (int l = 0; l < 4; l++) {
        // fused lin_l|lin_r GEMM: [N,256] @ [256,512]
        GEMM(gg4, bA16, W16_LIN + l * 131072, blin + l * 512, (float*)nullptr,
             bB16, bC16, (const float*)nullptr, 256, 512, 0, 0);
        if (l == 0) cudaStreamWaitEvent(0, evJoin, 0);  // join CSR before first gat
        k_gat<<<(NN + 7) / 8, 256>>>(bB16, bC16, bA, att + l * 256,
                                     gbias + l * 256, bD);
        k_ln_finalize<<<1, 1024>>>(NN);
        k_ln_norm<<<2048, 256>>>(bD, (float*)nullptr, bD16, n1w + l * 256,
                                 n1b + l * 256);
        GEMM(gg, bD16, W16_D2 + l * 65536, d2b + l * 256, bE, bE16,
             (__nv_bfloat16*)nullptr, (const float*)nullptr, 256, 256, 1, 0);
        // d3 GEMM with fused residual add (h2 + h3) and LN partials
        GEMM(gg, bE16, W16_D3 + l * 65536, d3b + l * 256, bD, (__nv_bfloat16*)nullptr,
             (__nv_bfloat16*)nullptr, bE, 256, 256, 0, 1);
        k_ln_finalize<<<1, 1024>>>(NPART);
        k_ln_norm<<<2048, 256>>>(bD, bA, bA16, n3w + l * 256, n3b + l * 256);
    }

    // post MLP
    GEMM(gg, bA16, W16_POST1, post1_b, bD, (__nv_bfloat16*)nullptr,
         (__nv_bfloat16*)nullptr, (const float*)nullptr, 256, 256, 0, 0);
    k_post2<<<(NN + 7) / 8, 256>>>(bD, post2_w, post2_b);

    // link prediction
    k_link<<<4096, 256>>>(li, link_w, link_b, out);
}

// round 17
// speedup vs baseline: 1.0518x; 1.0260x over previous
#include <cuda_runtime.h>
#include <cuda_bf16.h>
#include <math.h>
#include <stdint.h>

#define NN 50000
#define EE 800000
#define ET 850000      // EE + NN self loops
#define ELINK 1000000
#define PI_2 1.57079632679489662f

// ---------------- device scratch (allocation-free contract) ----------------
__device__ float g_bufD[(size_t)NN * 256];  // d3 out / n-LN input
__device__ float g_bufE[(size_t)NN * 256];  // h2
__device__ float g_hf[(size_t)NN * 32];

__device__ __nv_bfloat16 g_xcat16[(size_t)NN * 384];
__device__ __nv_bfloat16 g_bA16[(size_t)NN * 256];  // h (bf16 trunk)
__device__ __nv_bfloat16 g_bB16[(size_t)NN * 256];  // hl / pre1-temp
__device__ __nv_bfloat16 g_bC16[(size_t)NN * 256];  // hr
__device__ __nv_bfloat16 g_bD16[(size_t)NN * 256];  // h1
__device__ __nv_bfloat16 g_bE16[(size_t)NN * 256];  // h2

// bf16 weight arena. LIN region holds per-layer fused [K=256, 512] matrices
// (cols 0-255 = lin_l, cols 256-511 = lin_r).
#define W16_PRE1 0
#define W16_PRE2 98304
#define W16_LIN  163840
#define W16_D2   688128
#define W16_D3   950272
#define W16_POST1 1212416
#define W16_TOTAL 1277952
__device__ __nv_bfloat16 g_w16[W16_TOTAL];
__device__ float g_blin[4 * 512];   // fused lin bias per layer

__device__ int g_deg[NN];
__device__ int g_off[NN + 1];
__device__ int g_pos[NN];
__device__ int g_csr_src[ET];
__device__ int g_bsum[64];
__device__ float g_red[131072];
__device__ float g_stats[2];   // mu, rsig

// ---------------- weight conversion fp32 -> bf16 (+ fused lin layout) -------
__global__ void k_wconv(const float* p1, const float* p2, const float* ll,
                        const float* lr, const float* d2, const float* d3,
                        const float* po1, const float* llb, const float* lrb) {
    int i = blockIdx.x * blockDim.x + threadIdx.x;
    if (i >= W16_TOTAL + 2048) return;
    if (i >= W16_TOTAL) {
        int j = i - W16_TOTAL;
        int layer = j >> 9, c = j & 511;
        g_blin[j] = (c < 256) ? llb[layer * 256 + c] : lrb[layer * 256 + (c - 256)];
        return;
    }
    float v;
    if (i < W16_PRE2) v = p1[i - W16_PRE1];
    else if (i < W16_LIN) v = p2[i - W16_PRE2];
    else if (i < W16_D2) {
        int l = i - W16_LIN;
        int layer = l >> 17;
        int lm = l & 131071;
        int k = lm >> 9;
        int c = lm & 511;
        const float* src = (c < 256) ? ll : lr;
        v = src[layer * 65536 + k * 256 + (c & 255)];
    }
    else if (i < W16_D3) v = d2[i - W16_D2];
    else if (i < W16_POST1) v = d3[i - W16_D3];
    else v = po1[i - W16_POST1];
    g_w16[i] = __float2bfloat16(v);
}

// ---------------- CSR build ----------------
__global__ void k_init_deg() {
    int i = blockIdx.x * blockDim.x + threadIdx.x;
    if (i < NN) g_deg[i] = 1;  // self loop
}

__global__ void k_count(const int* __restrict__ ei) {
    int e = blockIdx.x * blockDim.x + threadIdx.x;
    if (e < EE) atomicAdd(&g_deg[ei[EE + e]], 1);
}

__global__ void k_scan1() {
    int b = blockIdx.x, t = threadIdx.x;
    int i = b * 1024 + t;
    int d = (i < NN) ? g_deg[i] : 0;
    int lane = t & 31, wid = t >> 5;
    int v = d;
#pragma unroll
    for (int o = 1; o < 32; o <<= 1) {
        int u = __shfl_up_sync(0xffffffffu, v, o);
        if (lane >= o) v += u;
    }
    __shared__ int ws[32];
    if (lane == 31) ws[wid] = v;
    __syncthreads();
    if (wid == 0) {
        int w = ws[lane];
#pragma unroll
        for (int o = 1; o < 32; o <<= 1) {
            int u = __shfl_up_sync(0xffffffffu, w, o);
            if (lane >= o) w += u;
        }
        ws[lane] = w;
    }
    __syncthreads();
    int incl = v + (wid ? ws[wid - 1] : 0);
    if (i < NN) g_off[i] = incl - d;
    if (t == 1023) g_bsum[b] = incl;
}

__global__ void k_scan2(int nblk) {
    int run = 0;
    for (int i = 0; i < nblk; i++) {
        int d = g_bsum[i];
        g_bsum[i] = run;
        run += d;
    }
}

__global__ void k_scan3() {
    int b = blockIdx.x, t = threadIdx.x;
    int i = b * 1024 + t;
    if (i < NN) {
        int off = g_off[i] + g_bsum[b];
        g_off[i] = off;
        g_pos[i] = off;
    }
    if (i == 0) g_off[NN] = ET;
}

__global__ void k_fill(const int* __restrict__ ei) {
    int i = blockIdx.x * blockDim.x + threadIdx.x;
    if (i < EE) {
        int s = ei[i];
        int d = ei[EE + i];
        int p = atomicAdd(&g_pos[d], 1);
        g_csr_src[p] = s;
    } else if (i < ET) {
        int n = i - EE;
        int p = atomicAdd(&g_pos[n], 1);
        g_csr_src[p] = n;
    }
}

// ---------------- time embedding + concat (bf16 out) ----------------
__global__ void k_te(const float* __restrict__ x, const float* __restrict__ t,
                     const float* __restrict__ tw, const float* __restrict__ tb) {
    int n = blockIdx.x;
    int j = threadIdx.x;
    if (j < 128) {
        g_xcat16[(size_t)n * 384 + j] = __float2bfloat16(x[(size_t)n * 128 + j]);
    } else {
        int jj = j - 128;
        float a = t[n] * (1.0f / 1000.0f);
        float sa, ca;
        sincosf(a * PI_2, &sa, &ca);
        float v = sa * tw[jj] + ca * tw[256 + jj] + a * tw[512 + jj] + tb[jj];
        v = v / (1.0f + __expf(-v));  // swish
        g_xcat16[(size_t)n * 384 + j] = __float2bfloat16(v);
    }
}

// ---------------- bf16 tensor-core GEMM, 3-stage pipeline (round-8 proven) --
#define A_STRIDE_B 80    // bytes per A smem row (64B data + 16B pad)
#define B_STRIDE_B 272   // bytes per B smem row (256B data + 16B pad)
#define A_BYTES (128 * A_STRIDE_B)   // 10240
#define B_BYTES (32 * B_STRIDE_B)    // 8704
#define STAGE_BYTES (A_BYTES + B_BYTES)
#define GEMM_SMEM_BYTES (3 * STAGE_BYTES)  // 56832

__global__ void __launch_bounds__(256, 2)
k_gemm_bf16(const __nv_bfloat16* __restrict__ A, const __nv_bfloat16* __restrict__ B,
            const float* __restrict__ bias, float* __restrict__ Cf,
            __nv_bfloat16* __restrict__ Ch, __nv_bfloat16* __restrict__ Ch2,
            const float* __restrict__ addC, int M, int K, int ldb,
            int relu, int red) {
    extern __shared__ char sm[];
    char* aBuf[3] = {sm, sm + STAGE_BYTES, sm + 2 * STAGE_BYTES};
    char* bBuf[3] = {sm + A_BYTES, sm + STAGE_BYTES + A_BYTES,
                     sm + 2 * STAGE_BYTES + A_BYTES};

    int tid = threadIdx.x;
    int lane = tid & 31;
    int w = tid >> 5;
    int wm = (w >> 2) * 64;
    int wn = (w & 3) * 32;
    int g = lane >> 2;
    int cc = lane & 3;
    int row0 = blockIdx.x * 128;
    int col0 = blockIdx.y * 128;

    __nv_bfloat16* Cht = (Ch2 && col0 >= 256) ? Ch2 : Ch;
    int cOff = (Ch2 && col0 >= 256) ? 256 : 0;

    float acc[4][4][4];
#pragma unroll
    for (int mt = 0; mt < 4; mt++)
#pragma unroll
        for (int nt = 0; nt < 4; nt++)
#pragma unroll
            for (int i = 0; i < 4; i++) acc[mt][nt][i] = 0.f;

    int NC = K >> 5;

    int a_row0 = tid >> 2, a_cw = tid & 3;
    int b_kr0 = tid >> 4, b_cw = tid & 15;

    int lm15 = lane & 15;
    int lhi = (lane >> 4) << 4;
    unsigned int a_lm_off = (unsigned int)((wm + lm15) * A_STRIDE_B + lhi);
    unsigned int b_lm_off = (unsigned int)(lm15 * B_STRIDE_B + wn * 2 + lhi);

#define ISSUE_CHUNK16(buf, kb)                                                        \
    {                                                                                 \
        char* as_ = aBuf[buf];                                                        \
        char* bs_ = bBuf[buf];                                                        \
        _Pragma("unroll") for (int p = 0; p < 2; p++) {                               \
            int row = a_row0 + p * 64;                                                \
            const __nv_bfloat16* src = A + (size_t)(row0 + row) * K + (kb) + a_cw * 8;\
            unsigned int dst = (unsigned int)__cvta_generic_to_shared(                \
                as_ + row * A_STRIDE_B + a_cw * 16);                                  \
            int sz = (row0 + row < M) ? 16 : 0;                                       \
            asm volatile("cp.async.ca.shared.global [%0], [%1], 16, %2;" ::           \
                             "r"(dst), "l"(src), "r"(sz));                            \
        }                                                                             \
        _Pragma("unroll") for (int p = 0; p < 2; p++) {                               \
            int kr = b_kr0 + p * 16;                                                  \
            const __nv_bfloat16* src =                                                \
                B + (size_t)((kb) + kr) * ldb + col0 + b_cw * 8;                      \
            unsigned int dst = (unsigned int)__cvta_generic_to_shared(                \
                bs_ + kr * B_STRIDE_B + b_cw * 16);                                   \
            asm volatile("cp.async.ca.shared.global [%0], [%1], 16, %2;" ::           \
                             "r"(dst), "l"(src), "r"(16));                            \
        }                                                                             \
        asm volatile("cp.async.commit_group;");                                       \
    }

    ISSUE_CHUNK16(0, 0);
    ISSUE_CHUNK16(1, 32);

    for (int c = 0; c < NC; c++) {
        if (c + 1 < NC) {
            asm volatile("cp.async.wait_group 1;");
        } else {
            asm volatile("cp.async.wait_group 0;");
        }
        __syncthreads();
        if (c + 2 < NC) {
            int nb = (c + 2) % 3;
            ISSUE_CHUNK16(nb, (c + 2) * 32);
        }

        int cb3 = c % 3;
        unsigned int as_base = (unsigned int)__cvta_generic_to_shared(aBuf[cb3]);
        unsigned int bs_base = (unsigned int)__cvta_generic_to_shared(bBuf[cb3]);

#pragma unroll
        for (int ks = 0; ks < 2; ks++) {
            unsigned int af[4][4], bf[2][4];
#pragma unroll
            for (int mt = 0; mt < 4; mt++) {
                unsigned int addr = as_base + a_lm_off + mt * 16 * A_STRIDE_B + ks * 32;
                asm volatile(
                    "ldmatrix.sync.aligned.m8n8.x4.shared.b16 {%0,%1,%2,%3}, [%4];"
                    : "=r"(af[mt][0]), "=r"(af[mt][1]), "=r"(af[mt][2]), "=r"(af[mt][3])
                    : "r"(addr));
            }
#pragma unroll
            for (int ntp = 0; ntp < 2; ntp++) {
                unsigned int addr = bs_base + b_lm_off + ks * 16 * B_STRIDE_B + ntp * 32;
                asm volatile(
                    "ldmatrix.sync.aligned.m8n8.x4.trans.shared.b16 {%0,%1,%2,%3}, [%4];"
                    : "=r"(bf[ntp][0]), "=r"(bf[ntp][1]), "=r"(bf[ntp][2]), "=r"(bf[ntp][3])
                    : "r"(addr));
            }
#pragma unroll
            for (int mt = 0; mt < 4; mt++)
#pragma unroll
                for (int nt = 0; nt < 4; nt++) {
                    int ntp = nt >> 1;
                    int ro = (nt & 1) * 2;
                    asm volatile(
                        "mma.sync.aligned.m16n8k16.row.col.f32.bf16.bf16.f32 "
                        "{%0,%1,%2,%3}, {%4,%5,%6,%7}, {%8,%9}, {%0,%1,%2,%3};"
                        : "+f"(acc[mt][nt][0]), "+f"(acc[mt][nt][1]),
                          "+f"(acc[mt][nt][2]), "+f"(acc[mt][nt][3])
                        : "r"(af[mt][0]), "r"(af[mt][1]), "r"(af[mt][2]),
                          "r"(af[mt][3]), "r"(bf[ntp][ro]), "r"(bf[ntp][ro + 1]));
                }
        }
    }

    // epilogue
    float s1 = 0.f, s2 = 0.f;
#pragma unroll
    for (int mt = 0; mt < 4; mt++) {
        int r0 = row0 + wm + mt * 16 + g;
        int r1 = r0 + 8;
#pragma unroll
        for (int nt = 0; nt < 4; nt++) {
            int cb = col0 + wn + nt * 8 + cc * 2;
            float b0 = bias[cb], b1 = bias[cb + 1];
            float v00 = acc[mt][nt][0] + b0, v01 = acc[mt][nt][1] + b1;
            float v10 = acc[mt][nt][2] + b0, v11 = acc[mt][nt][3] + b1;
            int co = cb - cOff;
            if (addC) {
                if (r0 < M) {
                    float2 a0 = *(const float2*)&addC[(size_t)r0 * 256 + co];
                    v00 += a0.x; v01 += a0.y;
                }
                if (r1 < M) {
                    float2 a1 = *(const float2*)&addC[(size_t)r1 * 256 + co];
                    v10 += a1.x; v11 += a1.y;
                }
            }
            if (relu) {
                v00 = fmaxf(v00, 0.f); v01 = fmaxf(v01, 0.f);
                v10 = fmaxf(v10, 0.f); v11 = fmaxf(v11, 0.f);
            }
            if (r0 < M) {
                if (Cf) *(float2*)&Cf[(size_t)r0 * 256 + co] = make_float2(v00, v01);
                if (Cht) {
                    unsigned int pk;
                    asm("cvt.rn.bf16x2.f32 %0, %1, %2;" : "=r"(pk) : "f"(v01), "f"(v00));
                    *(unsigned int*)&Cht[(size_t)r0 * 256 + co] = pk;
                }
                s1 += v00 + v01;
                s2 += v00 * v00 + v01 * v01;
            }
            if (r1 < M) {
                if (Cf) *(float2*)&Cf[(size_t)r1 * 256 + co] = make_float2(v10, v11);
                if (Cht) {
                    unsigned int pk;
                    asm("cvt.rn.bf16x2.f32 %0, %1, %2;" : "=r"(pk) : "f"(v11), "f"(v10));
                    *(unsigned int*)&Cht[(size_t)r1 * 256 + co] = pk;
                }
                s1 += v10 + v11;
                s2 += v10 * v10 + v11 * v11;
            }
        }
    }
    if (red) {
        __shared__ float sh1[8], sh2[8];
#pragma unroll
        for (int o = 16; o; o >>= 1) {
            s1 += __shfl_xor_sync(0xffffffffu, s1, o);
            s2 += __shfl_xor_sync(0xffffffffu, s2, o);
        }
        if (lane == 0) { sh1[w] = s1; sh2[w] = s2; }
        __syncthreads();
        if (tid == 0) {
            float A_ = 0.f, B_ = 0.f;
#pragma unroll
            for (int i = 0; i < 8; i++) { A_ += sh1[i]; B_ += sh2[i]; }
            int part = blockIdx.y * gridDim.x + blockIdx.x;
            g_red[2 * part] = A_;
            g_red[2 * part + 1] = B_;
        }
    }
}

// ---------------- GATv2: warp per node, bf16 residual trunk -----------------
__device__ __forceinline__ void bf8_to_f(uint4 u, float* v) {
    const __nv_bfloat162* p = (const __nv_bfloat162*)&u;
#pragma unroll
    for (int i = 0; i < 4; i++) {
        float2 f = __bfloat1622float2(p[i]);
        v[2 * i] = f.x;
        v[2 * i + 1] = f.y;
    }
}

__global__ void __launch_bounds__(256)
k_gat(const __nv_bfloat16* __restrict__ hl, const __nv_bfloat16* __restrict__ hr,
      const __nv_bfloat16* __restrict__ h16, const float* __restrict__ att,
      const float* __restrict__ gbias, float* __restrict__ y) {
    int lane = threadIdx.x & 31;
    int n = blockIdx.x * 8 + (threadIdx.x >> 5);
    if (n >= NN) return;
    int jb = lane * 8;

    float hrv[8], attv[8];
    bf8_to_f(*(const uint4*)&hr[(size_t)n * 256 + jb], hrv);
    *(float4*)&attv[0] = *(const float4*)&att[jb];
    *(float4*)&attv[4] = *(const float4*)&att[jb + 4];

    float accv[8];
#pragma unroll
    for (int i = 0; i < 8; i++) accv[i] = 0.f;
    float m = -INFINITY, z = 0.f;

    int k0 = g_off[n], k1 = g_off[n + 1];
    uint4 cur = *(const uint4*)&hl[(size_t)g_csr_src[k0] * 256 + jb];

    for (int k = k0; k < k1; k++) {
        uint4 nxt = cur;
        if (k + 1 < k1)
            nxt = *(const uint4*)&hl[(size_t)g_csr_src[k + 1] * 256 + jb];
        float v[8];
        bf8_to_f(cur, v);
        float p = 0.f;
#pragma unroll
        for (int i = 0; i < 8; i++) {
            float sv = v[i] + hrv[i];
            sv = sv > 0.f ? sv : 0.2f * sv;
            p = fmaf(sv, attv[i], p);
        }
        p += __shfl_xor_sync(0xffffffffu, p, 1);
        p += __shfl_xor_sync(0xffffffffu, p, 2);
        float mn = fmaxf(m, p);
        float sc = __expf(m - mn);
        float wgt = __expf(p - mn);
#pragma unroll
        for (int i = 0; i < 8; i++) accv[i] = accv[i] * sc + wgt * v[i];
        z = z * sc + wgt;
        m = mn;
        cur = nxt;
    }

    float invz = 1.f / (z + 1e-16f);
    float gb[8], hh[8], outv[8];
    *(float4*)&gb[0] = *(const float4*)&gbias[jb];
    *(float4*)&gb[4] = *(const float4*)&gbias[jb + 4];
    bf8_to_f(*(const uint4*)&h16[(size_t)n * 256 + jb], hh);
    float s1 = 0.f, s2 = 0.f;
#pragma unroll
    for (int i = 0; i < 8; i++) {
        float o = accv[i] * invz + gb[i] + hh[i];
        outv[i] = o;
        s1 += o;
        s2 += o * o;
    }
    *(float4*)&y[(size_t)n * 256 + jb] = *(float4*)&outv[0];
    *(float4*)&y[(size_t)n * 256 + jb + 4] = *(float4*)&outv[4];

#pragma unroll
    for (int o = 16; o; o >>= 1) {
        s1 += __shfl_xor_sync(0xffffffffu, s1, o);
        s2 += __shfl_xor_sync(0xffffffffu, s2, o);
    }
    if (lane == 0) {
        g_red[2 * n] = s1;
        g_red[2 * n + 1] = s2;
    }
}

__global__ void k_ln_finalize(int npart) {
    __shared__ double sa[1024], sb[1024];
    int t = threadIdx.x;
    double a = 0.0, b = 0.0;
    for (int i = t; i < npart; i += 1024) {
        a += (double)g_red[2 * i];
        b += (double)g_red[2 * i + 1];
    }
    sa[t] = a;
    sb[t] = b;
    __syncthreads();
    for (int o = 512; o; o >>= 1) {
        if (t < o) { sa[t] += sa[t + o]; sb[t] += sb[t + o]; }
        __syncthreads();
    }
    if (t == 0) {
        double inv = 1.0 / ((double)NN * 256.0);
        double mu = sa[0] * inv;
        double var = sb[0] * inv - mu * mu;
        g_stats[0] = (float)mu;
        g_stats[1] = (float)(1.0 / sqrt(var + 1e-5));
    }
}

__global__ void __launch_bounds__(256)
k_ln_norm(const float* __restrict__ in, float* __restrict__ outf,
          __nv_bfloat16* __restrict__ outh,
          const float* __restrict__ wl, const float* __restrict__ bl) {
    float mu = g_stats[0], rs = g_stats[1];
    size_t total = (size_t)NN * 128;  // pairs
    for (size_t i = (size_t)blockIdx.x * blockDim.x + threadIdx.x; i < total;
         i += (size_t)gridDim.x * blockDim.x) {
        size_t e = i * 2;
        int c = (int)(e & 255);
        float2 v = *(const float2*)&in[e];
        float o0 = (v.x - mu) * rs * wl[c] + bl[c];
        float o1 = (v.y - mu) * rs * wl[c + 1] + bl[c + 1];
        if (outf) *(float2*)&outf[e] = make_float2(o0, o1);
        if (outh) {
            unsigned int pk;
            asm("cvt.rn.bf16x2.f32 %0, %1, %2;" : "=r"(pk) : "f"(o1), "f"(o0));
            *(unsigned int*)&outh[e] = pk;
        }
    }
}

// ---------------- post2: [N,256] @ [256,32] + b ----------------
__global__ void __launch_bounds__(256)
k_post2(const float* __restrict__ Hin, const float* __restrict__ Wp,
        const float* __restrict__ bp) {
    __shared__ float ws[256 * 32];
    __shared__ float hs[8 * 256];
    int tid = threadIdx.x;
    for (int i = tid; i < 256 * 32; i += 256) ws[i] = Wp[i];
    int row0 = blockIdx.x * 8;
    for (int i = tid; i < 8 * 256; i += 256) {
        int r = row0 + (i >> 8);
        hs[i] = (r < NN) ? Hin[(size_t)r * 256 + (i & 255)] : 0.f;
    }
    __syncthreads();
    int r = tid >> 5, c = tid & 31;
    float acc = 0.f;
#pragma unroll 8
    for (int k = 0; k < 256; k++) acc += hs[r * 256 + k] * ws[k * 32 + c];
    int row = row0 + r;
    if (row < NN) g_hf[(size_t)row * 32 + c] = acc + bp[c];
}

// ---------------- link predictor ----------------
__global__ void __launch_bounds__(256)
k_link(const int* __restrict__ li, const float* __restrict__ lw,
       const float* __restrict__ lb, float* __restrict__ out) {
    int lane = threadIdx.x & 31;
    int wid = (blockIdx.x * blockDim.x + threadIdx.x) >> 5;
    int nw = (gridDim.x * blockDim.x) >> 5;
    float w = lw[lane];
    float bb = lb[0];
    for (int e = wid; e < ELINK; e += nw) {
        int s = li[e];
        int d = li[ELINK + e];
        float p = g_hf[(size_t)s * 32 + lane] * g_hf[(size_t)d * 32 + lane] * w;
#pragma unroll
        for (int o = 16; o; o >>= 1) p += __shfl_xor_sync(0xffffffffu, p, o);
        if (lane == 0) out[e] = 1.f / (1.f + __expf(-(p + bb)));
    }
}

// ---------------- orchestration ----------------
extern "C" void kernel_launch(void* const* d_in, const int* in_sizes, int n_in,
                              void* d_out, int out_size) {
    const float* x = (const float*)d_in[0];
    const float* t = (const float*)d_in[1];
    const int* ei = (const int*)d_in[2];
    const int* li = (const int*)d_in[3];
    const float* te_w = (const float*)d_in[4];
    const float* te_b = (const float*)d_in[5];
    const float* pre1_b = (const float*)d_in[7];
    const float* pre2_b = (const float*)d_in[9];
    const float* lin_l = (const float*)d_in[10];
    const float* lin_l_b = (const float*)d_in[11];
    const float* lin_r = (const float*)d_in[12];
    const float* lin_r_b = (const float*)d_in[13];
    const float* att = (const float*)d_in[14];
    const float* gbias = (const float*)d_in[15];
    const float* n1w = (const float*)d_in[16];
    const float* n1b = (const float*)d_in[17];
    const float* d2b = (const float*)d_in[19];
    const float* d3b = (const float*)d_in[21];
    const float* n3w = (const float*)d_in[22];
    const float* n3b = (const float*)d_in[23];
    const float* post1_b = (const float*)d_in[25];
    const float* post2_w = (const float*)d_in[26];
    const float* post2_b = (const float*)d_in[27];
    const float* link_w = (const float*)d_in[28];
    const float* link_b = (const float*)d_in[29];
    float* out = (float*)d_out;
    (void)in_sizes; (void)n_in; (void)out_size;

    float *bD, *bE, *blin;
    cudaGetSymbolAddress((void**)&bD, g_bufD);
    cudaGetSymbolAddress((void**)&bE, g_bufE);
    cudaGetSymbolAddress((void**)&blin, g_blin);
    __nv_bfloat16 *xcat16, *bA16, *bB16, *bC16, *bD16, *bE16, *w16;
    cudaGetSymbolAddress((void**)&xcat16, g_xcat16);
    cudaGetSymbolAddress((void**)&bA16, g_bA16);
    cudaGetSymbolAddress((void**)&bB16, g_bB16);
    cudaGetSymbolAddress((void**)&bC16, g_bC16);
    cudaGetSymbolAddress((void**)&bD16, g_bD16);
    cudaGetSymbolAddress((void**)&bE16, g_bE16);
    cudaGetSymbolAddress((void**)&w16, g_w16);

    static int inited = 0;
    static cudaStream_t s2;
    static cudaEvent_t evFork, evW, evJoin;
    if (!inited) {
        cudaFuncSetAttribute(k_gemm_bf16, cudaFuncAttributeMaxDynamicSharedMemorySize,
                             GEMM_SMEM_BYTES);
        cudaStreamCreateWithFlags(&s2, cudaStreamNonBlocking);
        cudaEventCreateWithFlags(&evFork, cudaEventDisableTiming);
        cudaEventCreateWithFlags(&evW, cudaEventDisableTiming);
        cudaEventCreateWithFlags(&evJoin, cudaEventDisableTiming);
        inited = 1;
    }

    dim3 gg((NN + 127) / 128, 2);
    dim3 gg4((NN + 127) / 128, 4);
    const int NPART = ((NN + 127) / 128) * 2;
#define GEMM(grid_, A_, Woff_, bias_, Cf_, Ch_, Ch2_, addC_, K_, ldb_, relu_, red_) \
    k_gemm_bf16<<<grid_, 256, GEMM_SMEM_BYTES>>>(A_, w16 + (Woff_), bias_, Cf_,     \
                                                 Ch_, Ch2_, addC_, NN, K_, ldb_,    \
                                                 relu_, red_)

    // ---- fork: wconv + CSR build run on s2, overlapping te on main ----
    cudaEventRecord(evFork, 0);
    cudaStreamWaitEvent(s2, evFork, 0);
    {
        k_wconv<<<(W16_TOTAL + 2048 + 255) / 256, 256, 0, s2>>>(
            (const float*)d_in[6], (const float*)d_in[8], lin_l, lin_r,
            (const float*)d_in[18], (const float*)d_in[20], (const float*)d_in[24],
            lin_l_b, lin_r_b);
        cudaEventRecord(evW, s2);
        const int SCAN_BLKS = (NN + 1023) / 1024;
        k_init_deg<<<(NN + 255) / 256, 256, 0, s2>>>();
        k_count<<<(EE + 255) / 256, 256, 0, s2>>>(ei);
        k_scan1<<<SCAN_BLKS, 1024, 0, s2>>>();
        k_scan2<<<1, 1, 0, s2>>>(SCAN_BLKS);
        k_scan3<<<SCAN_BLKS, 1024, 0, s2>>>();
        k_fill<<<(ET + 255) / 256, 256, 0, s2>>>(ei);
        cudaEventRecord(evJoin, s2);
    }

    // main stream: embed, then pre MLP (needs wconv)
    k_te<<<NN, 384>>>(x, t, te_w, te_b);
    cudaStreamWaitEvent(0, evW, 0);
    GEMM(gg, xcat16, W16_PRE1, pre1_b, (float*)nullptr, bB16,
         (__nv_bfloat16*)nullptr, (const float*)nullptr, 384, 256, 0, 0);
    GEMM(gg, bB16, W16_PRE2, pre2_b, (float*)nullptr, bA16,
         (__nv_bfloat16*)nullptr, (const float*)nullptr, 256, 256, 0, 0);

    for (int l = 0; l < 4; l++) {
        // fused lin_l|lin_r GEMM: [N,256] @ [256,512]
        GEMM(gg4, bA16, W16_LIN + l * 131072, blin + l * 512, (float*)nullptr,
             bB16, bC16, (const float*)nullptr, 256, 512, 0, 0);
        if (l == 0) cudaStreamWaitEvent(0, evJoin, 0);  // join CSR before first gat
        k_gat<<<(NN + 7) / 8, 256>>>(bB16, bC16, bA16, att + l * 256,
                                     gbias + l * 256, bD);
        k_ln_finalize<<<1, 1024>>>(NN);
        k_ln_norm<<<2048, 256>>>(bD, (float*)nullptr, bD16, n1w + l * 256,
                                 n1b + l * 256);
        GEMM(gg, bD16, W16_D2 + l * 65536, d2b + l * 256, bE, bE16,
             (__nv_bfloat16*)nullptr, (const float*)nullptr, 256, 256, 1, 0);
        // d3 GEMM with fused residual add (h2 + h3) and LN partials
        GEMM(gg, bE16, W16_D3 + l * 65536, d3b + l * 256, bD, (__nv_bfloat16*)nullptr,
             (__nv_bfloat16*)nullptr, bE, 256, 256, 0, 1);
        k_ln_finalize<<<1, 1024>>>(NPART);
        k_ln_norm<<<2048, 256>>>(bD, (float*)nullptr, bA16, n3w + l * 256,
                                 n3b + l * 256);
    }

    // post MLP
    GEMM(gg, bA16, W16_POST1, post1_b, bD, (__nv_bfloat16*)nullptr,
         (__nv_bfloat16*)nullptr, (const float*)nullptr, 256, 256, 0, 0);
    k_post2<<<(NN + 7) / 8, 256>>>(bD, post2_w, post2_b);

    // link prediction
    k_link<<<4096, 256>>>(li, link_w, link_b, out);
}